// round 6
// baseline (speedup 1.0000x reference)
#include <cuda_runtime.h>
#include <math.h>

#define MM 4096
#define WORDD 4096
#define NWH 2
#define RH 4
#define EPSV 0.001f
#define LCHUNK 32
#define LNCH 128   // 4096 / LCHUNK

// ---------------- scratch (device globals; allocation-free) ----------------
__device__ __align__(16) float g_wv[NWH*WORDD];
__device__ __align__(16) float g_ev[NWH*WORDD];
__device__ __align__(16) float g_wk[NWH*WORDD];
__device__ __align__(16) float g_rk[RH*WORDD];
__device__ __align__(16) float g_small[64]; // fg[0..3] ag[4..5] wg[6..7] rm[8..27] ws[28..29] rs[30..33]
__device__ __align__(16) float g_dot[NWH*MM];
__device__ __align__(16) float g_memnorm[MM];
__device__ __align__(16) float g_ww[NWH*MM];
__device__ __align__(16) float g_rdot[RH*MM];
__device__ __align__(16) float g_newnorm[MM];
__device__ __align__(16) float g_fwd[RH*NWH*MM];
__device__ __align__(16) float g_bwd[RH*NWH*MM];
__device__ __align__(16) float g_rw[RH*MM];
__device__ __align__(16) float g_part_bwd[NWH*LNCH*RH*MM];  // 16 MB fixed-order partials
__device__ __align__(16) float g_part_rw[16*RH*WORDD];      // 1 MB

__device__ __forceinline__ float wred(float v){
    #pragma unroll
    for (int o=16;o;o>>=1) v += __shfl_xor_sync(0xFFFFFFFFu,v,o);
    return v;
}
// grouped 4-value reduce: 6 shfls. lanes 0-7 sum(a), 8-15 sum(b), 16-23 sum(c), 24-31 sum(d)
__device__ __forceinline__ float gred4(float a, float b, float c, float d, int lane){
    float x1 = (lane&16)? a : c;
    float x2 = (lane&16)? b : d;
    float r1 = __shfl_xor_sync(0xFFFFFFFFu, x1, 16);
    float r2 = __shfl_xor_sync(0xFFFFFFFFu, x2, 16);
    float va = ((lane&16)? c : a) + r1;
    float vb = ((lane&16)? d : b) + r2;
    float y = (lane&8)? va : vb;
    float r = __shfl_xor_sync(0xFFFFFFFFu, y, 8);
    float v = ((lane&8)? vb : va) + r;
    #pragma unroll
    for (int o=4;o;o>>=1) v += __shfl_xor_sync(0xFFFFFFFFu, v, o);
    return v;
}
// grouped 2-value reduce: 6 shfls. lanes 0-15 sum(a), 16-31 sum(b)
__device__ __forceinline__ float gred2(float a, float b, int lane){
    float x = (lane&16)? a : b;
    float r = __shfl_xor_sync(0xFFFFFFFFu, x, 16);
    float v = ((lane&16)? b : a) + r;
    #pragma unroll
    for (int o=8;o;o>>=1) v += __shfl_xor_sync(0xFFFFFFFFu, v, o);
    return v;
}

// ---------------- kernel 1: all linear layers (warp-per-row matvec) --------
__global__ void k_matvec(const float* __restrict__ x,
    const float* __restrict__ Wwv, const float* __restrict__ bwv,
    const float* __restrict__ Wev, const float* __restrict__ bev,
    const float* __restrict__ Wfg, const float* __restrict__ bfg,
    const float* __restrict__ Wag, const float* __restrict__ bag,
    const float* __restrict__ Wwg, const float* __restrict__ bwg,
    const float* __restrict__ Wrm, const float* __restrict__ brm,
    const float* __restrict__ Wwk, const float* __restrict__ bwk,
    const float* __restrict__ Wws, const float* __restrict__ bws,
    const float* __restrict__ Wrk, const float* __restrict__ brk,
    const float* __restrict__ Wrs, const float* __restrict__ brs)
{
    int warp = (blockIdx.x*blockDim.x + threadIdx.x) >> 5;
    int lane = threadIdx.x & 31;
    if (warp >= 40994) return;
    const float* W; const float* b; float* out; int row; int act;
    if (warp < 8192)       { W=Wwv; b=bwv; out=g_wv; row=warp;       act=0; }
    else if (warp < 16384) { W=Wev; b=bev; out=g_ev; row=warp-8192;  act=1; }
    else if (warp < 24576) { W=Wwk; b=bwk; out=g_wk; row=warp-16384; act=1; }
    else if (warp < 40960) { W=Wrk; b=brk; out=g_rk; row=warp-24576; act=0; }
    else {
        int r = warp - 40960;
        if (r < 4)       { W=Wfg; b=bfg; out=g_small+0;  row=r;    act=1; }
        else if (r < 6)  { W=Wag; b=bag; out=g_small+4;  row=r-4;  act=1; }
        else if (r < 8)  { W=Wwg; b=bwg; out=g_small+6;  row=r-6;  act=1; }
        else if (r < 28) { W=Wrm; b=brm; out=g_small+8;  row=r-8;  act=1; }
        else if (r < 30) { W=Wws; b=bws; out=g_small+28; row=r-28; act=0; }
        else             { W=Wrs; b=brs; out=g_small+30; row=r-30; act=0; }
    }
    const float4* Wr = (const float4*)(W + (size_t)row*1024);
    const float4* x4 = (const float4*)x;
    float s = 0.f;
    #pragma unroll 8
    for (int i = lane; i < 256; i += 32) {
        float4 w4 = Wr[i], xx = x4[i];
        s += w4.x*xx.x + w4.y*xx.y + w4.z*xx.z + w4.w*xx.w;
    }
    s = wred(s);
    if (lane==0) {
        s += b[row];
        if (act) s = 1.f/(1.f+expf(-s));
        out[row] = s;
    }
}

// ------------- kernel 2: dot(write_keys, memory) + memory row norms --------
__global__ void __launch_bounds__(1024) k_memdot(const float* __restrict__ memory) {
    __shared__ float s_part[32][3*32];
    int tid = threadIdx.x, lane = tid&31, wid = tid>>5;
    const float4* wk4 = (const float4*)g_wk;
    float4 k0 = __ldg(&wk4[tid]);
    float4 k1 = __ldg(&wk4[1024+tid]);
    int base = blockIdx.x*32;
    float4 vA_n = __ldg((const float4*)(memory + (size_t)base*WORDD) + tid);
    float4 vB_n = __ldg((const float4*)(memory + (size_t)(base+1)*WORDD) + tid);
    #pragma unroll 1
    for (int ii = 0; ii < 32; ii += 2) {
        float4 vA = vA_n, vB = vB_n;
        if (ii < 30) {
            vA_n = __ldg((const float4*)(memory + (size_t)(base+ii+2)*WORDD) + tid);
            vB_n = __ldg((const float4*)(memory + (size_t)(base+ii+3)*WORDD) + tid);
        }
        float dA0 = vA.x*k0.x+vA.y*k0.y+vA.z*k0.z+vA.w*k0.w;
        float dA1 = vA.x*k1.x+vA.y*k1.y+vA.z*k1.z+vA.w*k1.w;
        float nnA = vA.x*vA.x+vA.y*vA.y+vA.z*vA.z+vA.w*vA.w;
        float dB0 = vB.x*k0.x+vB.y*k0.y+vB.z*k0.z+vB.w*k0.w;
        float dB1 = vB.x*k1.x+vB.y*k1.y+vB.z*k1.z+vB.w*k1.w;
        float nnB = vB.x*vB.x+vB.y*vB.y+vB.z*vB.z+vB.w*vB.w;
        float dv = gred4(dA0,dA1,dB0,dB1,lane);
        float nv = gred2(nnA,nnB,lane);
        if (lane==0)  s_part[ii][wid]      = dv;
        if (lane==8)  s_part[ii][32+wid]   = dv;
        if (lane==16) s_part[ii+1][wid]    = dv;
        if (lane==24) s_part[ii+1][32+wid] = dv;
        if (lane==0)  s_part[ii][64+wid]   = nv;
        if (lane==16) s_part[ii+1][64+wid] = nv;
    }
    __syncthreads();
    if (tid < 96) {
        int row = tid/3, q = tid - row*3;
        float s = 0.f;
        #pragma unroll
        for (int k=0;k<32;k++) s += s_part[row][q*32+k];
        int m = base + row;
        if (q==0) g_dot[m]=s; else if (q==1) g_dot[MM+m]=s; else g_memnorm[m]=sqrtf(s);
    }
}

// ------------- kernel 3: serial core (usage, allocation sort, ww, prec) ----
__global__ void k_small(const float* __restrict__ prev_rw,
                        const float* __restrict__ prev_ww,
                        const float* __restrict__ prev_prec,
                        const float* __restrict__ prev_usage,
                        float* __restrict__ out_ww,
                        float* __restrict__ out_prec,
                        float* __restrict__ out_usage)
{
    extern __shared__ float sm[];
    float* s_usage = sm;                 // M
    float* s_a     = sm + MM;            // M
    float* s_cw    = sm + 2*MM;          // M
    unsigned long long* s_pack = (unsigned long long*)(sm + 4*MM); // M x 8B
    __shared__ float red[32];
    __shared__ float s_wsum2[32];
    __shared__ float s_wpre[32];
    __shared__ float s_bc;
    const int T = 1024;
    int tid = threadIdx.x; int lane = tid&31, wid = tid>>5;

    float fg0=g_small[0],fg1=g_small[1],fg2=g_small[2],fg3=g_small[3];

    for (int m=tid;m<MM;m+=T){
        float u = prev_usage[m];
        u = u + (1.f-u)*(1.f - prev_ww[m]*prev_ww[MM+m]);
        float p = (fg0*prev_rw[m])*(fg1*prev_rw[MM+m])*(fg2*prev_rw[2*MM+m])*(fg3*prev_rw[3*MM+m]);
        s_usage[m] = u*(1.f - p);
    }
    __syncthreads();

    for (int head=0; head<NWH; head++) {
        float kn = 0.f;
        for (int d=tid; d<WORDD; d+=T){ float k = g_wk[head*WORDD+d]; kn += k*k; }
        kn = wred(kn);
        if (lane==0) red[wid]=kn;
        __syncthreads();
        if (tid==0){ float s=0; for(int k=0;k<32;k++) s+=red[k]; s_bc = sqrtf(s);}
        __syncthreads();
        kn = s_bc;
        float ws = g_small[28+head];
        float beta = 1.f + log1pf(expf(ws));

        float mx = -3.4e38f;
        for (int m=tid;m<MM;m+=T){
            float l = g_dot[head*MM+m]/(kn*g_memnorm[m]+EPSV)*beta;
            mx = fmaxf(mx,l);
        }
        #pragma unroll
        for (int o=16;o;o>>=1) mx = fmaxf(mx,__shfl_xor_sync(0xFFFFFFFFu,mx,o));
        if (lane==0) red[wid]=mx;
        __syncthreads();
        if (tid==0){ float s=-3.4e38f; for(int k=0;k<32;k++) s=fmaxf(s,red[k]); s_bc=s;}
        __syncthreads();
        mx = s_bc;
        float sume=0.f;
        for (int m=tid;m<MM;m+=T){
            float l = g_dot[head*MM+m]/(kn*g_memnorm[m]+EPSV)*beta;
            float e = expf(l-mx);
            s_cw[m]=e; sume+=e;
        }
        sume = wred(sume);
        if (lane==0) red[wid]=sume;
        __syncthreads();
        if (tid==0){ float s=0; for(int k=0;k<32;k++) s+=red[k]; s_bc=s;}
        __syncthreads();
        float inv = 1.f/s_bc;
        for (int m=tid;m<MM;m+=T) s_cw[m] *= inv;

        // stable ascending argsort: packed (u,idx) uint64 bitonic
        for (int m=tid;m<MM;m+=T){
            float u = EPSV + (1.f-EPSV)*s_usage[m];
            s_pack[m] = ((unsigned long long)__float_as_uint(u) << 32) | (unsigned)m;
        }
        __syncthreads();
        for (int k=2;k<=MM;k<<=1){
            int j = k>>1;
            for (; j>=32; j>>=1){
                for (int t=tid;t<MM;t+=T){
                    int l = t ^ j;
                    if (l > t){
                        unsigned long long a=s_pack[t], b=s_pack[l];
                        bool asc = ((t & k)==0);
                        if (asc ? (a>b) : (a<b)){ s_pack[t]=b; s_pack[l]=a; }
                    }
                }
                __syncthreads();
            }
            unsigned long long v[4];
            #pragma unroll
            for (int c=0;c<4;c++) v[c]=s_pack[tid+(c<<10)];
            for (; j>=1; j>>=1){
                #pragma unroll
                for (int c=0;c<4;c++){
                    unsigned long long pv = __shfl_xor_sync(0xFFFFFFFFu, v[c], j);
                    int e = tid + (c<<10);
                    bool asc = ((e & k)==0);
                    bool isLow = ((tid & j)==0);
                    bool take = isLow ? (asc ? (v[c]>pv) : (v[c]<pv))
                                      : (asc ? (v[c]<pv) : (v[c]>pv));
                    if (take) v[c]=pv;
                }
            }
            #pragma unroll
            for (int c=0;c<4;c++) s_pack[tid+(c<<10)]=v[c];
            __syncthreads();
        }

        // cumprod scan + alloc scatter
        {
            int base = tid*4;
            unsigned long long p0=s_pack[base],p1=s_pack[base+1],p2=s_pack[base+2],p3=s_pack[base+3];
            float x0=__uint_as_float((unsigned)(p0>>32));
            float x1=__uint_as_float((unsigned)(p1>>32));
            float x2=__uint_as_float((unsigned)(p2>>32));
            float x3=__uint_as_float((unsigned)(p3>>32));
            float c0=x0, c1=c0*x1, c2=c1*x2, c3=c2*x3;
            float t3=c3;
            #pragma unroll
            for (int o=1;o<32;o<<=1){ float n=__shfl_up_sync(0xFFFFFFFFu,t3,o); if (lane>=o) t3*=n; }
            float warpExcl = __shfl_up_sync(0xFFFFFFFFu,t3,1); if (lane==0) warpExcl=1.f;
            if (lane==31) s_wsum2[wid]=t3;
            __syncthreads();
            if (tid<32){
                float w = s_wsum2[tid];
                float tw=w;
                #pragma unroll
                for (int o=1;o<32;o<<=1){ float n=__shfl_up_sync(0xFFFFFFFFu,tw,o); if (tid>=o) tw*=n; }
                float excl = __shfl_up_sync(0xFFFFFFFFu,tw,1); if (tid==0) excl=1.f;
                s_wpre[tid]=excl;
            }
            __syncthreads();
            float pre = s_wpre[wid]*warpExcl;
            int i0=(int)(p0&0xFFFFFFFFull), i1=(int)(p1&0xFFFFFFFFull);
            int i2=(int)(p2&0xFFFFFFFFull), i3=(int)(p3&0xFFFFFFFFull);
            s_a[i0]=(1.f-x0)*pre;
            s_a[i1]=(1.f-x1)*pre*c0;
            s_a[i2]=(1.f-x2)*pre*c1;
            s_a[i3]=(1.f-x3)*pre*c2;
            __syncthreads();
        }

        float ag = g_small[4+head], wg = g_small[6+head];
        float wsum = 0.f;
        for (int m=tid;m<MM;m+=T){
            float a = s_a[m];
            float cw = s_cw[m];
            float w = wg*(ag*a + (1.f-ag)*cw);
            g_ww[head*MM+m] = w;
            out_ww[head*MM+m] = w;
            wsum += w;
            float u = s_usage[m];
            s_usage[m] = u + (1.f - u)*(ag*wg)*a;
        }
        wsum = wred(wsum);
        if (lane==0) red[wid]=wsum;
        __syncthreads();
        if (tid==0){ float s=0; for(int k=0;k<32;k++) s+=red[k]; s_bc=s;}
        __syncthreads();
        float oms = 1.f - s_bc;
        for (int m=tid;m<MM;m+=T)
            out_prec[head*MM+m] = oms*prev_prec[head*MM+m] + g_ww[head*MM+m];
        __syncthreads();
    }
    for (int m=tid;m<MM;m+=T) out_usage[m]=s_usage[m];
}

// ------------- kernel 4+5 fused: newmem tile (even blocks) / link chunk (odd)
__global__ void __launch_bounds__(512) k_big(
    const float* __restrict__ memory, float* __restrict__ out_nm,
    const float* __restrict__ prev_link, const float* __restrict__ prev_prec,
    const float* __restrict__ prev_rw, float* __restrict__ out_link)
{
    __shared__ float s_part[16][5*16];     // newmem reduction
    __shared__ float s_fred[LCHUNK][4][16]; // link fwd reduction
    int tid=threadIdx.x, lane=tid&31, wid=tid>>5;
    if ((blockIdx.x & 1)==0){
        // ================= newmem: 16-row tile =================
        int base = (blockIdx.x>>1)*16;
        const float4* ev4=(const float4*)g_ev;
        const float4* wv4=(const float4*)g_wv;
        const float4* rk4=(const float4*)g_rk;
        int ca = tid, cb = 512+tid;
        float4 e0a=__ldg(&ev4[ca]),      e0b=__ldg(&ev4[cb]);
        float4 e1a=__ldg(&ev4[1024+ca]), e1b=__ldg(&ev4[1024+cb]);
        float4 a0a=__ldg(&wv4[ca]),      a0b=__ldg(&wv4[cb]);
        float4 a1a=__ldg(&wv4[1024+ca]), a1b=__ldg(&wv4[1024+cb]);
        float4 k0a=__ldg(&rk4[ca]),      k0b=__ldg(&rk4[cb]);
        float4 k1a=__ldg(&rk4[1024+ca]), k1b=__ldg(&rk4[1024+cb]);
        float4 k2a=__ldg(&rk4[2048+ca]), k2b=__ldg(&rk4[2048+cb]);
        float4 k3a=__ldg(&rk4[3072+ca]), k3b=__ldg(&rk4[3072+cb]);
        float4 va_n = __ldg((const float4*)(memory+(size_t)base*WORDD) + ca);
        float4 vb_n = __ldg((const float4*)(memory+(size_t)base*WORDD) + cb);
        #pragma unroll 1
        for (int ii=0; ii<16; ii++){
            int m = base+ii;
            float4 va=va_n, vb=vb_n;
            if (ii<15){
                va_n = __ldg((const float4*)(memory+(size_t)(m+1)*WORDD) + ca);
                vb_n = __ldg((const float4*)(memory+(size_t)(m+1)*WORDD) + cb);
            }
            float w0=__ldg(&g_ww[m]), w1=__ldg(&g_ww[MM+m]);
            float4 oa, ob;
            oa.x = va.x*((1.f-w0*e0a.x)*(1.f-w1*e1a.x)) + w0*a0a.x + w1*a1a.x;
            oa.y = va.y*((1.f-w0*e0a.y)*(1.f-w1*e1a.y)) + w0*a0a.y + w1*a1a.y;
            oa.z = va.z*((1.f-w0*e0a.z)*(1.f-w1*e1a.z)) + w0*a0a.z + w1*a1a.z;
            oa.w = va.w*((1.f-w0*e0a.w)*(1.f-w1*e1a.w)) + w0*a0a.w + w1*a1a.w;
            ob.x = vb.x*((1.f-w0*e0b.x)*(1.f-w1*e1b.x)) + w0*a0b.x + w1*a1b.x;
            ob.y = vb.y*((1.f-w0*e0b.y)*(1.f-w1*e1b.y)) + w0*a0b.y + w1*a1b.y;
            ob.z = vb.z*((1.f-w0*e0b.z)*(1.f-w1*e1b.z)) + w0*a0b.z + w1*a1b.z;
            ob.w = vb.w*((1.f-w0*e0b.w)*(1.f-w1*e1b.w)) + w0*a0b.w + w1*a1b.w;
            ((float4*)(out_nm+(size_t)m*WORDD))[ca]=oa;
            ((float4*)(out_nm+(size_t)m*WORDD))[cb]=ob;
            float r0 = oa.x*k0a.x+oa.y*k0a.y+oa.z*k0a.z+oa.w*k0a.w
                     + ob.x*k0b.x+ob.y*k0b.y+ob.z*k0b.z+ob.w*k0b.w;
            float r1 = oa.x*k1a.x+oa.y*k1a.y+oa.z*k1a.z+oa.w*k1a.w
                     + ob.x*k1b.x+ob.y*k1b.y+ob.z*k1b.z+ob.w*k1b.w;
            float r2 = oa.x*k2a.x+oa.y*k2a.y+oa.z*k2a.z+oa.w*k2a.w
                     + ob.x*k2b.x+ob.y*k2b.y+ob.z*k2b.z+ob.w*k2b.w;
            float r3 = oa.x*k3a.x+oa.y*k3a.y+oa.z*k3a.z+oa.w*k3a.w
                     + ob.x*k3b.x+ob.y*k3b.y+ob.z*k3b.z+ob.w*k3b.w;
            float nn = oa.x*oa.x+oa.y*oa.y+oa.z*oa.z+oa.w*oa.w
                     + ob.x*ob.x+ob.y*ob.y+ob.z*ob.z+ob.w*ob.w;
            float rv = gred4(r0,r1,r2,r3,lane);
            float nv = wred(nn);
            if ((lane&7)==0) s_part[ii][(lane>>3)*16+wid] = rv;
            if (lane==0)     s_part[ii][64+wid] = nv;
        }
        __syncthreads();
        if (tid < 80){
            int row=tid/5, q=tid-row*5;
            float s=0.f;
            #pragma unroll
            for (int k=0;k<16;k++) s += s_part[row][q*16+k];
            int m = base + row;
            if (q<4) g_rdot[q*MM+m]=s; else g_newnorm[m]=sqrtf(s);
        }
    } else {
        // ================= link: 32-row chunk =================
        int b = blockIdx.x>>1;      // 0..255
        int w = b>>7;               // head
        int chunk = b&127;
        int i0 = chunk*LCHUNK;
        const float4* ww4 = (const float4*)(g_ww + w*MM);
        const float4* pp4 = (const float4*)(prev_prec + w*MM);
        const float4* pr4 = (const float4*)prev_rw;
        float4 wwa=__ldg(&ww4[tid]),       wwb=__ldg(&ww4[512+tid]);
        float4 ppa=__ldg(&pp4[tid]),       ppb=__ldg(&pp4[512+tid]);
        float4 pa0=__ldg(&pr4[tid]),       pb0=__ldg(&pr4[512+tid]);
        float4 pa1=__ldg(&pr4[1024+tid]),  pb1=__ldg(&pr4[1536+tid]);
        float4 pa2=__ldg(&pr4[2048+tid]),  pb2=__ldg(&pr4[2560+tid]);
        float4 pa3=__ldg(&pr4[3072+tid]),  pb3=__ldg(&pr4[3584+tid]);
        float bw0[8],bw1[8],bw2[8],bw3[8];
        #pragma unroll
        for (int c=0;c<8;c++){ bw0[c]=0.f;bw1[c]=0.f;bw2[c]=0.f;bw3[c]=0.f; }
        int ja = tid*4, jb = (512+tid)*4;
        const float4* plbase = (const float4*)(prev_link + (size_t)w*MM*MM);
        float4 pA_n = __ldcs(plbase + (size_t)i0*1024 + tid);
        float4 pB_n = __ldcs(plbase + (size_t)i0*1024 + 512 + tid);
        #pragma unroll 1
        for (int ii=0; ii<LCHUNK; ii++){
            int i = i0+ii;
            float4 pA = pA_n, pB = pB_n;
            if (ii<LCHUNK-1){
                pA_n = __ldcs(plbase + (size_t)(i+1)*1024 + tid);
                pB_n = __ldcs(plbase + (size_t)(i+1)*1024 + 512 + tid);
            }
            float wwi = __ldg(&g_ww[w*MM+i]);
            float pri0=__ldg(&prev_rw[i]),      pri1=__ldg(&prev_rw[MM+i]);
            float pri2=__ldg(&prev_rw[2*MM+i]), pri3=__ldg(&prev_rw[3*MM+i]);
            float f0=0.f,f1=0.f,f2=0.f,f3=0.f;
            float4 oA, oB;
            {
                float l = (1.f-wwi-wwa.x)*pA.x + wwi*ppa.x; if (ja+0==i) l=0.f; oA.x=l;
                f0+=pa0.x*l; f1+=pa1.x*l; f2+=pa2.x*l; f3+=pa3.x*l;
                bw0[0]+=pri0*l; bw1[0]+=pri1*l; bw2[0]+=pri2*l; bw3[0]+=pri3*l;
            }
            {
                float l = (1.f-wwi-wwa.y)*pA.y + wwi*ppa.y; if (ja+1==i) l=0.f; oA.y=l;
                f0+=pa0.y*l; f1+=pa1.y*l; f2+=pa2.y*l; f3+=pa3.y*l;
                bw0[1]+=pri0*l; bw1[1]+=pri1*l; bw2[1]+=pri2*l; bw3[1]+=pri3*l;
            }
            {
                float l = (1.f-wwi-wwa.z)*pA.z + wwi*ppa.z; if (ja+2==i) l=0.f; oA.z=l;
                f0+=pa0.z*l; f1+=pa1.z*l; f2+=pa2.z*l; f3+=pa3.z*l;
                bw0[2]+=pri0*l; bw1[2]+=pri1*l; bw2[2]+=pri2*l; bw3[2]+=pri3*l;
            }
            {
                float l = (1.f-wwi-wwa.w)*pA.w + wwi*ppa.w; if (ja+3==i) l=0.f; oA.w=l;
                f0+=pa0.w*l; f1+=pa1.w*l; f2+=pa2.w*l; f3+=pa3.w*l;
                bw0[3]+=pri0*l; bw1[3]+=pri1*l; bw2[3]+=pri2*l; bw3[3]+=pri3*l;
            }
            {
                float l = (1.f-wwi-wwb.x)*pB.x + wwi*ppb.x; if (jb+0==i) l=0.f; oB.x=l;
                f0+=pb0.x*l; f1+=pb1.x*l; f2+=pb2.x*l; f3+=pb3.x*l;
                bw0[4]+=pri0*l; bw1[4]+=pri1*l; bw2[4]+=pri2*l; bw3[4]+=pri3*l;
            }
            {
                float l = (1.f-wwi-wwb.y)*pB.y + wwi*ppb.y; if (jb+1==i) l=0.f; oB.y=l;
                f0+=pb0.y*l; f1+=pb1.y*l; f2+=pb2.y*l; f3+=pb3.y*l;
                bw0[5]+=pri0*l; bw1[5]+=pri1*l; bw2[5]+=pri2*l; bw3[5]+=pri3*l;
            }
            {
                float l = (1.f-wwi-wwb.z)*pB.z + wwi*ppb.z; if (jb+2==i) l=0.f; oB.z=l;
                f0+=pb0.z*l; f1+=pb1.z*l; f2+=pb2.z*l; f3+=pb3.z*l;
                bw0[6]+=pri0*l; bw1[6]+=pri1*l; bw2[6]+=pri2*l; bw3[6]+=pri3*l;
            }
            {
                float l = (1.f-wwi-wwb.w)*pB.w + wwi*ppb.w; if (jb+3==i) l=0.f; oB.w=l;
                f0+=pb0.w*l; f1+=pb1.w*l; f2+=pb2.w*l; f3+=pb3.w*l;
                bw0[7]+=pri0*l; bw1[7]+=pri1*l; bw2[7]+=pri2*l; bw3[7]+=pri3*l;
            }
            float4* lo = (float4*)(out_link + ((size_t)w*MM+i)*MM);
            __stcs(lo + tid, oA);
            __stcs(lo + 512 + tid, oB);
            float fv = gred4(f0,f1,f2,f3,lane);
            if ((lane&7)==0) s_fred[ii][lane>>3][wid]=fv;
        }
        __syncthreads();
        if (tid < LCHUNK*4){
            int row = tid>>2, r = tid&3;
            float s=0.f;
            #pragma unroll
            for (int k=0;k<16;k++) s += s_fred[row][r][k];
            g_fwd[(r*NWH + w)*MM + i0 + row] = s;
        }
        size_t pb = (size_t)(w*LNCH + chunk)*4;
        ((float4*)(g_part_bwd + (pb+0)*MM))[tid]     = make_float4(bw0[0],bw0[1],bw0[2],bw0[3]);
        ((float4*)(g_part_bwd + (pb+0)*MM))[512+tid] = make_float4(bw0[4],bw0[5],bw0[6],bw0[7]);
        ((float4*)(g_part_bwd + (pb+1)*MM))[tid]     = make_float4(bw1[0],bw1[1],bw1[2],bw1[3]);
        ((float4*)(g_part_bwd + (pb+1)*MM))[512+tid] = make_float4(bw1[4],bw1[5],bw1[6],bw1[7]);
        ((float4*)(g_part_bwd + (pb+2)*MM))[tid]     = make_float4(bw2[0],bw2[1],bw2[2],bw2[3]);
        ((float4*)(g_part_bwd + (pb+2)*MM))[512+tid] = make_float4(bw2[4],bw2[5],bw2[6],bw2[7]);
        ((float4*)(g_part_bwd + (pb+3)*MM))[tid]     = make_float4(bw3[0],bw3[1],bw3[2],bw3[3]);
        ((float4*)(g_part_bwd + (pb+3)*MM))[512+tid] = make_float4(bw3[4],bw3[5],bw3[6],bw3[7]);
    }
}

// ------------- kernel 6: reduce bwd partials (fixed order, deterministic) --
__global__ void k_bwdreduce(){
    int idx = blockIdx.x*blockDim.x + threadIdx.x; // 32768
    if (idx >= RH*NWH*MM) return;
    int m = idx & (MM-1);
    int w = (idx >> 12) & 1;
    int r = idx >> 13;
    float s=0.f;
    #pragma unroll 8
    for (int t=0;t<LNCH;t++)
        s += g_part_bwd[((size_t)(w*LNCH+t)*4 + r)*MM + m];
    g_bwd[idx]=s;
}

// ------------- kernel 7: read weights (content softmax + mode combine) -----
__global__ void k_readw(float* __restrict__ out_rw){
    __shared__ float s_e[MM];
    __shared__ float red[32];
    __shared__ float s_bc;
    const int T = 1024;
    int tid=threadIdx.x, lane=tid&31, wid=tid>>5;
    for (int r=0;r<RH;r++){
        float kn=0.f;
        for (int d=tid;d<WORDD;d+=T){ float k=g_rk[r*WORDD+d]; kn+=k*k; }
        kn = wred(kn);
        if (lane==0) red[wid]=kn;
        __syncthreads();
        if (tid==0){ float s=0; for(int k=0;k<32;k++) s+=red[k]; s_bc=sqrtf(s);}
        __syncthreads();
        kn=s_bc;
        float rs = g_small[30+r];
        float mx=-3.4e38f;
        for (int m=tid;m<MM;m+=T){
            float l = g_rdot[r*MM+m]/(kn*g_newnorm[m])*rs;
            mx=fmaxf(mx,l);
        }
        #pragma unroll
        for (int o=16;o;o>>=1) mx=fmaxf(mx,__shfl_xor_sync(0xFFFFFFFFu,mx,o));
        if (lane==0) red[wid]=mx;
        __syncthreads();
        if (tid==0){ float s=-3.4e38f; for(int k=0;k<32;k++) s=fmaxf(s,red[k]); s_bc=s;}
        __syncthreads();
        mx=s_bc;
        float sume=0.f;
        for (int m=tid;m<MM;m+=T){
            float l = g_rdot[r*MM+m]/(kn*g_newnorm[m])*rs;
            float e = expf(l-mx);
            s_e[m]=e; sume+=e;
        }
        sume = wred(sume);
        if (lane==0) red[wid]=sume;
        __syncthreads();
        if (tid==0){ float s=0; for(int k=0;k<32;k++) s+=red[k]; s_bc=s;}
        __syncthreads();
        float inv = 1.f/s_bc;
        float bm0=g_small[8+r*5+0], bm1=g_small[8+r*5+1];
        float fm0=g_small[8+r*5+2], fm1=g_small[8+r*5+3];
        float cm =g_small[8+r*5+4];
        for (int m=tid;m<MM;m+=T){
            float v = bm0*g_bwd[(r*2+0)*MM+m] + bm1*g_bwd[(r*2+1)*MM+m]
                    + fm0*g_fwd[(r*2+0)*MM+m] + fm1*g_fwd[(r*2+1)*MM+m]
                    + cm*s_e[m]*inv;
            g_rw[r*MM+m]=v; out_rw[r*MM+m]=v;
        }
        __syncthreads();
    }
}

// ------------- kernel 8: read_words partials -------------------------------
__global__ void k_readwords(const float* __restrict__ nm){
    __shared__ float s_rw[4][256];
    int d = blockIdx.x*256 + threadIdx.x;
    int m0 = blockIdx.y*256;
    #pragma unroll
    for (int r=0;r<4;r++) s_rw[r][threadIdx.x] = g_rw[r*MM + m0 + threadIdx.x];
    __syncthreads();
    float a0=0,a1=0,a2=0,a3=0;
    #pragma unroll 4
    for (int mm=0;mm<256;mm++){
        float v = nm[(size_t)(m0+mm)*WORDD + d];
        a0+=s_rw[0][mm]*v; a1+=s_rw[1][mm]*v; a2+=s_rw[2][mm]*v; a3+=s_rw[3][mm]*v;
    }
    g_part_rw[(blockIdx.y*4+0)*WORDD+d]=a0;
    g_part_rw[(blockIdx.y*4+1)*WORDD+d]=a1;
    g_part_rw[(blockIdx.y*4+2)*WORDD+d]=a2;
    g_part_rw[(blockIdx.y*4+3)*WORDD+d]=a3;
}

// ------------- kernel 9: reduce read_words partials ------------------------
__global__ void k_rwreduce(float* __restrict__ out_rwords){
    int idx = blockIdx.x*blockDim.x+threadIdx.x; // 16384
    if (idx >= RH*WORDD) return;
    int r = idx >> 12; int d = idx & (WORDD-1);
    float s=0.f;
    #pragma unroll
    for (int t=0;t<16;t++) s += g_part_rw[(t*4+r)*WORDD+d];
    out_rwords[idx]=s;
}

// ---------------------------------------------------------------------------
extern "C" void kernel_launch(void* const* d_in, const int* in_sizes, int n_in,
                              void* d_out, int out_size) {
    const float* x      = (const float*)d_in[0];
    const float* memory = (const float*)d_in[1];
    const float* prw    = (const float*)d_in[2];
    const float* pww    = (const float*)d_in[3];
    const float* plink  = (const float*)d_in[4];
    const float* pprec  = (const float*)d_in[5];
    const float* pusage = (const float*)d_in[6];

    float* out = (float*)d_out;
    float* o_rwords = out;                            // 4*4096
    float* o_nm     = out + 16384;                    // 4096*4096
    float* o_rw     = out + 16384 + 16777216;         // 4*4096
    float* o_ww     = o_rw + 16384;                   // 2*4096
    float* o_link   = o_ww + 8192;                    // 2*4096*4096
    float* o_prec   = o_link + 33554432;              // 2*4096
    float* o_usage  = o_prec + 8192;                  // 4096

    cudaFuncSetAttribute(k_small, cudaFuncAttributeMaxDynamicSharedMemorySize, 6*MM*4);

    // 1. all linears
    {
        int warps = 40994;
        int blocks = (warps*32 + 255)/256;
        k_matvec<<<blocks, 256>>>(x,
            (const float*)d_in[7],  (const float*)d_in[8],
            (const float*)d_in[9],  (const float*)d_in[10],
            (const float*)d_in[11], (const float*)d_in[12],
            (const float*)d_in[13], (const float*)d_in[14],
            (const float*)d_in[15], (const float*)d_in[16],
            (const float*)d_in[17], (const float*)d_in[18],
            (const float*)d_in[19], (const float*)d_in[20],
            (const float*)d_in[21], (const float*)d_in[22],
            (const float*)d_in[23], (const float*)d_in[24],
            (const float*)d_in[25], (const float*)d_in[26]);
    }
    // 2. write-key similarity dot + mem norms
    k_memdot<<<128, 1024>>>(memory);
    // 3. serial core
    k_small<<<1, 1024, 6*MM*4>>>(prw, pww, pprec, pusage, o_ww, o_prec, o_usage);
    // 4+5. fused: newmem tiles (even blocks) + link chunks (odd blocks)
    k_big<<<512, 512>>>(memory, o_nm, plink, pprec, prw, o_link);
    // 6. bwd partial reduce
    k_bwdreduce<<<128, 256>>>();
    // 7. read weights
    k_readw<<<1, 1024>>>(o_rw);
    // 8-9. read words
    k_readwords<<<dim3(16,16), 256>>>(o_nm);
    k_rwreduce<<<64, 256>>>(o_rwords);
}

// round 7
// speedup vs baseline: 1.0024x; 1.0024x over previous
#include <cuda_runtime.h>
#include <math.h>

#define MM 4096
#define WORDD 4096
#define NWH 2
#define RH 4
#define EPSV 0.001f
#define LCHUNK 64
#define LNCH 64   // 4096 / LCHUNK

// ---------------- scratch (device globals; allocation-free) ----------------
__device__ __align__(16) float g_wv[NWH*WORDD];
__device__ __align__(16) float g_ev[NWH*WORDD];
__device__ __align__(16) float g_wk[NWH*WORDD];
__device__ __align__(16) float g_rk[RH*WORDD];
__device__ __align__(16) float g_small[64]; // fg[0..3] ag[4..5] wg[6..7] rm[8..27] ws[28..29] rs[30..33]
__device__ __align__(16) float g_dot[NWH*MM];
__device__ __align__(16) float g_memnorm[MM];
__device__ __align__(16) float g_ww[NWH*MM];
__device__ __align__(16) float g_rdot[RH*MM];
__device__ __align__(16) float g_newnorm[MM];
__device__ __align__(16) float g_fwd[RH*NWH*MM];
__device__ __align__(16) float g_bwd[RH*NWH*MM];
__device__ __align__(16) float g_rw[RH*MM];
__device__ __align__(16) float g_part_bwd[NWH*LNCH*RH*MM];  // 8 MB fixed-order partials
__device__ __align__(16) float g_part_rw[16*RH*WORDD];      // 1 MB

__device__ __forceinline__ float wred(float v){
    #pragma unroll
    for (int o=16;o;o>>=1) v += __shfl_xor_sync(0xFFFFFFFFu,v,o);
    return v;
}
// grouped 4-value reduce: 6 shfls. lanes 0-7 sum(a), 8-15 sum(b), 16-23 sum(c), 24-31 sum(d)
__device__ __forceinline__ float gred4(float a, float b, float c, float d, int lane){
    float x1 = (lane&16)? a : c;
    float x2 = (lane&16)? b : d;
    float r1 = __shfl_xor_sync(0xFFFFFFFFu, x1, 16);
    float r2 = __shfl_xor_sync(0xFFFFFFFFu, x2, 16);
    float va = ((lane&16)? c : a) + r1;
    float vb = ((lane&16)? d : b) + r2;
    float y = (lane&8)? va : vb;
    float r = __shfl_xor_sync(0xFFFFFFFFu, y, 8);
    float v = ((lane&8)? vb : va) + r;
    #pragma unroll
    for (int o=4;o;o>>=1) v += __shfl_xor_sync(0xFFFFFFFFu, v, o);
    return v;
}
// grouped 2-value reduce: 6 shfls. lanes 0-15 sum(a), 16-31 sum(b)
__device__ __forceinline__ float gred2(float a, float b, int lane){
    float x = (lane&16)? a : b;
    float r = __shfl_xor_sync(0xFFFFFFFFu, x, 16);
    float v = ((lane&16)? b : a) + r;
    #pragma unroll
    for (int o=8;o;o>>=1) v += __shfl_xor_sync(0xFFFFFFFFu, v, o);
    return v;
}

// ---------------- kernel 1: linears, split into two phases -----------------
// phase 0 (A): W_wk rows + all scalar heads  (gates memdot/small)
// phase 1 (B): W_wv, W_ev, W_rk rows         (gates newmem/readw)
__global__ void k_matvec(int phase, const float* __restrict__ x,
    const float* __restrict__ Wwv, const float* __restrict__ bwv,
    const float* __restrict__ Wev, const float* __restrict__ bev,
    const float* __restrict__ Wfg, const float* __restrict__ bfg,
    const float* __restrict__ Wag, const float* __restrict__ bag,
    const float* __restrict__ Wwg, const float* __restrict__ bwg,
    const float* __restrict__ Wrm, const float* __restrict__ brm,
    const float* __restrict__ Wwk, const float* __restrict__ bwk,
    const float* __restrict__ Wws, const float* __restrict__ bws,
    const float* __restrict__ Wrk, const float* __restrict__ brk,
    const float* __restrict__ Wrs, const float* __restrict__ brs)
{
    int warp = (blockIdx.x*blockDim.x + threadIdx.x) >> 5;
    int lane = threadIdx.x & 31;
    const float* W; const float* b; float* out; int row; int act;
    if (phase == 0){
        if (warp >= 8226) return;
        if (warp < 8192) { W=Wwk; b=bwk; out=g_wk; row=warp; act=1; }
        else {
            int r = warp - 8192;
            if (r < 4)       { W=Wfg; b=bfg; out=g_small+0;  row=r;    act=1; }
            else if (r < 6)  { W=Wag; b=bag; out=g_small+4;  row=r-4;  act=1; }
            else if (r < 8)  { W=Wwg; b=bwg; out=g_small+6;  row=r-6;  act=1; }
            else if (r < 28) { W=Wrm; b=brm; out=g_small+8;  row=r-8;  act=1; }
            else if (r < 30) { W=Wws; b=bws; out=g_small+28; row=r-28; act=0; }
            else             { W=Wrs; b=brs; out=g_small+30; row=r-30; act=0; }
        }
    } else {
        if (warp >= 32768) return;
        if (warp < 8192)       { W=Wwv; b=bwv; out=g_wv; row=warp;       act=0; }
        else if (warp < 16384) { W=Wev; b=bev; out=g_ev; row=warp-8192;  act=1; }
        else                   { W=Wrk; b=brk; out=g_rk; row=warp-16384; act=0; }
    }
    const float4* Wr = (const float4*)(W + (size_t)row*1024);
    const float4* x4 = (const float4*)x;
    float s = 0.f;
    #pragma unroll 8
    for (int i = lane; i < 256; i += 32) {
        float4 w4 = Wr[i], xx = x4[i];
        s += w4.x*xx.x + w4.y*xx.y + w4.z*xx.z + w4.w*xx.w;
    }
    s = wred(s);
    if (lane==0) {
        s += b[row];
        if (act) s = 1.f/(1.f+expf(-s));
        out[row] = s;
    }
}

// ------------- kernel 2: dot(write_keys, memory) + memory row norms --------
__global__ void __launch_bounds__(1024) k_memdot(const float* __restrict__ memory) {
    __shared__ float s_part[32][3*32];
    int tid = threadIdx.x, lane = tid&31, wid = tid>>5;
    const float4* wk4 = (const float4*)g_wk;
    float4 k0 = __ldg(&wk4[tid]);
    float4 k1 = __ldg(&wk4[1024+tid]);
    int base = blockIdx.x*32;
    float4 vA_n = __ldg((const float4*)(memory + (size_t)base*WORDD) + tid);
    float4 vB_n = __ldg((const float4*)(memory + (size_t)(base+1)*WORDD) + tid);
    #pragma unroll 1
    for (int ii = 0; ii < 32; ii += 2) {
        float4 vA = vA_n, vB = vB_n;
        if (ii < 30) {
            vA_n = __ldg((const float4*)(memory + (size_t)(base+ii+2)*WORDD) + tid);
            vB_n = __ldg((const float4*)(memory + (size_t)(base+ii+3)*WORDD) + tid);
        }
        float dA0 = vA.x*k0.x+vA.y*k0.y+vA.z*k0.z+vA.w*k0.w;
        float dA1 = vA.x*k1.x+vA.y*k1.y+vA.z*k1.z+vA.w*k1.w;
        float nnA = vA.x*vA.x+vA.y*vA.y+vA.z*vA.z+vA.w*vA.w;
        float dB0 = vB.x*k0.x+vB.y*k0.y+vB.z*k0.z+vB.w*k0.w;
        float dB1 = vB.x*k1.x+vB.y*k1.y+vB.z*k1.z+vB.w*k1.w;
        float nnB = vB.x*vB.x+vB.y*vB.y+vB.z*vB.z+vB.w*vB.w;
        float dv = gred4(dA0,dA1,dB0,dB1,lane);
        float nv = gred2(nnA,nnB,lane);
        if (lane==0)  s_part[ii][wid]      = dv;
        if (lane==8)  s_part[ii][32+wid]   = dv;
        if (lane==16) s_part[ii+1][wid]    = dv;
        if (lane==24) s_part[ii+1][32+wid] = dv;
        if (lane==0)  s_part[ii][64+wid]   = nv;
        if (lane==16) s_part[ii+1][64+wid] = nv;
    }
    __syncthreads();
    if (tid < 96) {
        int row = tid/3, q = tid - row*3;
        float s = 0.f;
        #pragma unroll
        for (int k=0;k<32;k++) s += s_part[row][q*32+k];
        int m = base + row;
        if (q==0) g_dot[m]=s; else if (q==1) g_dot[MM+m]=s; else g_memnorm[m]=sqrtf(s);
    }
}

// ------------- kernel 3: serial core (usage, allocation sort, ww, prec) ----
__global__ void k_small(const float* __restrict__ prev_rw,
                        const float* __restrict__ prev_ww,
                        const float* __restrict__ prev_prec,
                        const float* __restrict__ prev_usage,
                        float* __restrict__ out_ww,
                        float* __restrict__ out_prec,
                        float* __restrict__ out_usage)
{
    extern __shared__ float sm[];
    float* s_usage = sm;                 // M
    float* s_a     = sm + MM;            // M
    float* s_cw    = sm + 2*MM;          // M
    unsigned long long* s_pack = (unsigned long long*)(sm + 4*MM); // M x 8B
    __shared__ float red[32];
    __shared__ float s_wsum2[32];
    __shared__ float s_wpre[32];
    __shared__ float s_bc;
    const int T = 1024;
    int tid = threadIdx.x; int lane = tid&31, wid = tid>>5;

    float fg0=g_small[0],fg1=g_small[1],fg2=g_small[2],fg3=g_small[3];

    for (int m=tid;m<MM;m+=T){
        float u = prev_usage[m];
        u = u + (1.f-u)*(1.f - prev_ww[m]*prev_ww[MM+m]);
        float p = (fg0*prev_rw[m])*(fg1*prev_rw[MM+m])*(fg2*prev_rw[2*MM+m])*(fg3*prev_rw[3*MM+m]);
        s_usage[m] = u*(1.f - p);
    }
    __syncthreads();

    for (int head=0; head<NWH; head++) {
        float kn = 0.f;
        for (int d=tid; d<WORDD; d+=T){ float k = g_wk[head*WORDD+d]; kn += k*k; }
        kn = wred(kn);
        if (lane==0) red[wid]=kn;
        __syncthreads();
        if (tid==0){ float s=0; for(int k=0;k<32;k++) s+=red[k]; s_bc = sqrtf(s);}
        __syncthreads();
        kn = s_bc;
        float ws = g_small[28+head];
        float beta = 1.f + log1pf(expf(ws));

        float mx = -3.4e38f;
        for (int m=tid;m<MM;m+=T){
            float l = g_dot[head*MM+m]/(kn*g_memnorm[m]+EPSV)*beta;
            mx = fmaxf(mx,l);
        }
        #pragma unroll
        for (int o=16;o;o>>=1) mx = fmaxf(mx,__shfl_xor_sync(0xFFFFFFFFu,mx,o));
        if (lane==0) red[wid]=mx;
        __syncthreads();
        if (tid==0){ float s=-3.4e38f; for(int k=0;k<32;k++) s=fmaxf(s,red[k]); s_bc=s;}
        __syncthreads();
        mx = s_bc;
        float sume=0.f;
        for (int m=tid;m<MM;m+=T){
            float l = g_dot[head*MM+m]/(kn*g_memnorm[m]+EPSV)*beta;
            float e = expf(l-mx);
            s_cw[m]=e; sume+=e;
        }
        sume = wred(sume);
        if (lane==0) red[wid]=sume;
        __syncthreads();
        if (tid==0){ float s=0; for(int k=0;k<32;k++) s+=red[k]; s_bc=s;}
        __syncthreads();
        float inv = 1.f/s_bc;
        for (int m=tid;m<MM;m+=T) s_cw[m] *= inv;

        // stable ascending argsort: packed (u,idx) uint64 bitonic
        for (int m=tid;m<MM;m+=T){
            float u = EPSV + (1.f-EPSV)*s_usage[m];
            s_pack[m] = ((unsigned long long)__float_as_uint(u) << 32) | (unsigned)m;
        }
        __syncthreads();
        for (int k=2;k<=MM;k<<=1){
            int j = k>>1;
            for (; j>=32; j>>=1){
                for (int t=tid;t<MM;t+=T){
                    int l = t ^ j;
                    if (l > t){
                        unsigned long long a=s_pack[t], b=s_pack[l];
                        bool asc = ((t & k)==0);
                        if (asc ? (a>b) : (a<b)){ s_pack[t]=b; s_pack[l]=a; }
                    }
                }
                __syncthreads();
            }
            unsigned long long v[4];
            #pragma unroll
            for (int c=0;c<4;c++) v[c]=s_pack[tid+(c<<10)];
            for (; j>=1; j>>=1){
                #pragma unroll
                for (int c=0;c<4;c++){
                    unsigned long long pv = __shfl_xor_sync(0xFFFFFFFFu, v[c], j);
                    int e = tid + (c<<10);
                    bool asc = ((e & k)==0);
                    bool isLow = ((tid & j)==0);
                    bool take = isLow ? (asc ? (v[c]>pv) : (v[c]<pv))
                                      : (asc ? (v[c]<pv) : (v[c]>pv));
                    if (take) v[c]=pv;
                }
            }
            #pragma unroll
            for (int c=0;c<4;c++) s_pack[tid+(c<<10)]=v[c];
            __syncthreads();
        }

        // cumprod scan + alloc scatter
        {
            int base = tid*4;
            unsigned long long p0=s_pack[base],p1=s_pack[base+1],p2=s_pack[base+2],p3=s_pack[base+3];
            float x0=__uint_as_float((unsigned)(p0>>32));
            float x1=__uint_as_float((unsigned)(p1>>32));
            float x2=__uint_as_float((unsigned)(p2>>32));
            float x3=__uint_as_float((unsigned)(p3>>32));
            float c0=x0, c1=c0*x1, c2=c1*x2, c3=c2*x3;
            float t3=c3;
            #pragma unroll
            for (int o=1;o<32;o<<=1){ float n=__shfl_up_sync(0xFFFFFFFFu,t3,o); if (lane>=o) t3*=n; }
            float warpExcl = __shfl_up_sync(0xFFFFFFFFu,t3,1); if (lane==0) warpExcl=1.f;
            if (lane==31) s_wsum2[wid]=t3;
            __syncthreads();
            if (tid<32){
                float w = s_wsum2[tid];
                float tw=w;
                #pragma unroll
                for (int o=1;o<32;o<<=1){ float n=__shfl_up_sync(0xFFFFFFFFu,tw,o); if (tid>=o) tw*=n; }
                float excl = __shfl_up_sync(0xFFFFFFFFu,tw,1); if (tid==0) excl=1.f;
                s_wpre[tid]=excl;
            }
            __syncthreads();
            float pre = s_wpre[wid]*warpExcl;
            int i0=(int)(p0&0xFFFFFFFFull), i1=(int)(p1&0xFFFFFFFFull);
            int i2=(int)(p2&0xFFFFFFFFull), i3=(int)(p3&0xFFFFFFFFull);
            s_a[i0]=(1.f-x0)*pre;
            s_a[i1]=(1.f-x1)*pre*c0;
            s_a[i2]=(1.f-x2)*pre*c1;
            s_a[i3]=(1.f-x3)*pre*c2;
            __syncthreads();
        }

        float ag = g_small[4+head], wg = g_small[6+head];
        float wsum = 0.f;
        for (int m=tid;m<MM;m+=T){
            float a = s_a[m];
            float cw = s_cw[m];
            float w = wg*(ag*a + (1.f-ag)*cw);
            g_ww[head*MM+m] = w;
            out_ww[head*MM+m] = w;
            wsum += w;
            float u = s_usage[m];
            s_usage[m] = u + (1.f - u)*(ag*wg)*a;
        }
        wsum = wred(wsum);
        if (lane==0) red[wid]=wsum;
        __syncthreads();
        if (tid==0){ float s=0; for(int k=0;k<32;k++) s+=red[k]; s_bc=s;}
        __syncthreads();
        float oms = 1.f - s_bc;
        for (int m=tid;m<MM;m+=T)
            out_prec[head*MM+m] = oms*prev_prec[head*MM+m] + g_ww[head*MM+m];
        __syncthreads();
    }
    for (int m=tid;m<MM;m+=T) out_usage[m]=s_usage[m];
}

// ------------- kernel 4: new_memory + fused rdot + new norms ---------------
__global__ void __launch_bounds__(1024) k_newmem(const float* __restrict__ memory,
                                                 float* __restrict__ out_nm){
    __shared__ float s_part[32][5*32];
    int tid=threadIdx.x, lane=tid&31, wid=tid>>5;
    const float4* ev4=(const float4*)g_ev;
    const float4* wv4=(const float4*)g_wv;
    const float4* rk4=(const float4*)g_rk;
    float4 e0=__ldg(&ev4[tid]),      e1=__ldg(&ev4[1024+tid]);
    float4 a0=__ldg(&wv4[tid]),      a1=__ldg(&wv4[1024+tid]);
    float4 k0=__ldg(&rk4[tid]),      k1=__ldg(&rk4[1024+tid]);
    float4 k2=__ldg(&rk4[2048+tid]), k3=__ldg(&rk4[3072+tid]);
    int base = blockIdx.x*32;
    float4 v_next = __ldg((const float4*)(memory+(size_t)base*WORDD) + tid);
    #pragma unroll 1
    for (int ii=0; ii<32; ii++){
        int m = base+ii;
        float4 v = v_next;
        if (ii<31) v_next = __ldg((const float4*)(memory+(size_t)(m+1)*WORDD) + tid);
        float w0=__ldg(&g_ww[m]), w1=__ldg(&g_ww[MM+m]);
        float4 o;
        o.x = v.x*((1.f-w0*e0.x)*(1.f-w1*e1.x)) + w0*a0.x + w1*a1.x;
        o.y = v.y*((1.f-w0*e0.y)*(1.f-w1*e1.y)) + w0*a0.y + w1*a1.y;
        o.z = v.z*((1.f-w0*e0.z)*(1.f-w1*e1.z)) + w0*a0.z + w1*a1.z;
        o.w = v.w*((1.f-w0*e0.w)*(1.f-w1*e1.w)) + w0*a0.w + w1*a1.w;
        ((float4*)(out_nm+(size_t)m*WORDD))[tid]=o;
        float r0 = o.x*k0.x+o.y*k0.y+o.z*k0.z+o.w*k0.w;
        float r1 = o.x*k1.x+o.y*k1.y+o.z*k1.z+o.w*k1.w;
        float r2 = o.x*k2.x+o.y*k2.y+o.z*k2.z+o.w*k2.w;
        float r3 = o.x*k3.x+o.y*k3.y+o.z*k3.z+o.w*k3.w;
        float nn = o.x*o.x+o.y*o.y+o.z*o.z+o.w*o.w;
        float rv = gred4(r0,r1,r2,r3,lane);
        float nv = wred(nn);
        if ((lane&7)==0) s_part[ii][(lane>>3)*32+wid] = rv;
        if (lane==0)     s_part[ii][128+wid] = nv;
    }
    __syncthreads();
    if (tid < 160){
        int row=tid/5, q=tid-row*5;
        float s=0.f;
        #pragma unroll
        for (int k=0;k<32;k++) s += s_part[row][q*32+k];
        int m = base + row;
        if (q<4) g_rdot[q*MM+m]=s; else g_newnorm[m]=sqrtf(s);
    }
}

// ------------- kernel 5: link update + fused fwd_w/bwd_w -------------------
__global__ void __launch_bounds__(1024,1) k_link(const float* __restrict__ prev_link,
                       const float* __restrict__ prev_prec,
                       const float* __restrict__ prev_rw,
                       float* __restrict__ out_link){
    __shared__ float s_fred[LCHUNK][4][32];
    int w = blockIdx.y;
    int tid=threadIdx.x, lane=tid&31, wid=tid>>5;
    const float4* ww4 = (const float4*)(g_ww + w*MM);
    const float4* pp4 = (const float4*)(prev_prec + w*MM);
    const float4* pr4 = (const float4*)prev_rw;
    float4 wwv = __ldg(&ww4[tid]);
    float4 ppv = __ldg(&pp4[tid]);
    float4 pc0 = __ldg(&pr4[tid]);
    float4 pc1 = __ldg(&pr4[1024+tid]);
    float4 pc2 = __ldg(&pr4[2048+tid]);
    float4 pc3 = __ldg(&pr4[3072+tid]);
    float bw0[4],bw1[4],bw2[4],bw3[4];
    #pragma unroll
    for (int c=0;c<4;c++){ bw0[c]=0.f;bw1[c]=0.f;bw2[c]=0.f;bw3[c]=0.f; }
    int i0 = blockIdx.x*LCHUNK;
    int j0 = tid*4;
    const float4* plbase = (const float4*)(prev_link + (size_t)w*MM*MM);
    float4 p_next = __ldcs(plbase + (size_t)i0*1024 + tid);
    #pragma unroll 1
    for (int ii=0; ii<LCHUNK; ii++){
        int i = i0+ii;
        float4 p = p_next;
        if (ii<LCHUNK-1) p_next = __ldcs(plbase + (size_t)(i+1)*1024 + tid);
        float wwi = __ldg(&g_ww[w*MM+i]);
        float pri0=__ldg(&prev_rw[i]),      pri1=__ldg(&prev_rw[MM+i]);
        float pri2=__ldg(&prev_rw[2*MM+i]), pri3=__ldg(&prev_rw[3*MM+i]);
        float f0=0.f,f1=0.f,f2=0.f,f3=0.f;
        float4 o;
        {
            float l = (1.f-wwi-wwv.x)*p.x + wwi*ppv.x; if (j0+0==i) l=0.f; o.x=l;
            f0+=pc0.x*l; f1+=pc1.x*l; f2+=pc2.x*l; f3+=pc3.x*l;
            bw0[0]+=pri0*l; bw1[0]+=pri1*l; bw2[0]+=pri2*l; bw3[0]+=pri3*l;
        }
        {
            float l = (1.f-wwi-wwv.y)*p.y + wwi*ppv.y; if (j0+1==i) l=0.f; o.y=l;
            f0+=pc0.y*l; f1+=pc1.y*l; f2+=pc2.y*l; f3+=pc3.y*l;
            bw0[1]+=pri0*l; bw1[1]+=pri1*l; bw2[1]+=pri2*l; bw3[1]+=pri3*l;
        }
        {
            float l = (1.f-wwi-wwv.z)*p.z + wwi*ppv.z; if (j0+2==i) l=0.f; o.z=l;
            f0+=pc0.z*l; f1+=pc1.z*l; f2+=pc2.z*l; f3+=pc3.z*l;
            bw0[2]+=pri0*l; bw1[2]+=pri1*l; bw2[2]+=pri2*l; bw3[2]+=pri3*l;
        }
        {
            float l = (1.f-wwi-wwv.w)*p.w + wwi*ppv.w; if (j0+3==i) l=0.f; o.w=l;
            f0+=pc0.w*l; f1+=pc1.w*l; f2+=pc2.w*l; f3+=pc3.w*l;
            bw0[3]+=pri0*l; bw1[3]+=pri1*l; bw2[3]+=pri2*l; bw3[3]+=pri3*l;
        }
        __stcs((float4*)(out_link + ((size_t)w*MM+i)*MM) + tid, o);
        float fv = gred4(f0,f1,f2,f3,lane);
        if ((lane&7)==0) s_fred[ii][lane>>3][wid]=fv;
    }
    __syncthreads();
    if (tid < LCHUNK*4){
        int row = tid>>2, r = tid&3;
        float s=0.f;
        #pragma unroll
        for (int k=0;k<32;k++) s += s_fred[row][r][k];
        g_fwd[(r*NWH + w)*MM + i0 + row] = s;
    }
    size_t pb = (size_t)(w*LNCH + blockIdx.x)*4;
    ((float4*)(g_part_bwd + (pb+0)*MM))[tid] = make_float4(bw0[0],bw0[1],bw0[2],bw0[3]);
    ((float4*)(g_part_bwd + (pb+1)*MM))[tid] = make_float4(bw1[0],bw1[1],bw1[2],bw1[3]);
    ((float4*)(g_part_bwd + (pb+2)*MM))[tid] = make_float4(bw2[0],bw2[1],bw2[2],bw2[3]);
    ((float4*)(g_part_bwd + (pb+3)*MM))[tid] = make_float4(bw3[0],bw3[1],bw3[2],bw3[3]);
}

// ------------- kernel 6: reduce bwd partials (fixed order, deterministic) --
__global__ void k_bwdreduce(){
    int idx = blockIdx.x*blockDim.x + threadIdx.x; // 32768
    if (idx >= RH*NWH*MM) return;
    int m = idx & (MM-1);
    int w = (idx >> 12) & 1;
    int r = idx >> 13;
    float s=0.f;
    #pragma unroll 8
    for (int t=0;t<LNCH;t++)
        s += g_part_bwd[((size_t)(w*LNCH+t)*4 + r)*MM + m];
    g_bwd[idx]=s;
}

// ------------- kernel 7: read weights (content softmax + mode combine) -----
__global__ void k_readw(float* __restrict__ out_rw){
    __shared__ float s_e[MM];
    __shared__ float red[32];
    __shared__ float s_bc;
    const int T = 1024;
    int tid=threadIdx.x, lane=tid&31, wid=tid>>5;
    for (int r=0;r<RH;r++){
        float kn=0.f;
        for (int d=tid;d<WORDD;d+=T){ float k=g_rk[r*WORDD+d]; kn+=k*k; }
        kn = wred(kn);
        if (lane==0) red[wid]=kn;
        __syncthreads();
        if (tid==0){ float s=0; for(int k=0;k<32;k++) s+=red[k]; s_bc=sqrtf(s);}
        __syncthreads();
        kn=s_bc;
        float rs = g_small[30+r];
        float mx=-3.4e38f;
        for (int m=tid;m<MM;m+=T){
            float l = g_rdot[r*MM+m]/(kn*g_newnorm[m])*rs;
            mx=fmaxf(mx,l);
        }
        #pragma unroll
        for (int o=16;o;o>>=1) mx=fmaxf(mx,__shfl_xor_sync(0xFFFFFFFFu,mx,o));
        if (lane==0) red[wid]=mx;
        __syncthreads();
        if (tid==0){ float s=-3.4e38f; for(int k=0;k<32;k++) s=fmaxf(s,red[k]); s_bc=s;}
        __syncthreads();
        mx=s_bc;
        float sume=0.f;
        for (int m=tid;m<MM;m+=T){
            float l = g_rdot[r*MM+m]/(kn*g_newnorm[m])*rs;
            float e = expf(l-mx);
            s_e[m]=e; sume+=e;
        }
        sume = wred(sume);
        if (lane==0) red[wid]=sume;
        __syncthreads();
        if (tid==0){ float s=0; for(int k=0;k<32;k++) s+=red[k]; s_bc=s;}
        __syncthreads();
        float inv = 1.f/s_bc;
        float bm0=g_small[8+r*5+0], bm1=g_small[8+r*5+1];
        float fm0=g_small[8+r*5+2], fm1=g_small[8+r*5+3];
        float cm =g_small[8+r*5+4];
        for (int m=tid;m<MM;m+=T){
            float v = bm0*g_bwd[(r*2+0)*MM+m] + bm1*g_bwd[(r*2+1)*MM+m]
                    + fm0*g_fwd[(r*2+0)*MM+m] + fm1*g_fwd[(r*2+1)*MM+m]
                    + cm*s_e[m]*inv;
            g_rw[r*MM+m]=v; out_rw[r*MM+m]=v;
        }
        __syncthreads();
    }
}

// ------------- kernel 8: read_words partials -------------------------------
__global__ void k_readwords(const float* __restrict__ nm){
    __shared__ float s_rw[4][256];
    int d = blockIdx.x*256 + threadIdx.x;
    int m0 = blockIdx.y*256;
    #pragma unroll
    for (int r=0;r<4;r++) s_rw[r][threadIdx.x] = g_rw[r*MM + m0 + threadIdx.x];
    __syncthreads();
    float a0=0,a1=0,a2=0,a3=0;
    #pragma unroll 4
    for (int mm=0;mm<256;mm++){
        float v = nm[(size_t)(m0+mm)*WORDD + d];
        a0+=s_rw[0][mm]*v; a1+=s_rw[1][mm]*v; a2+=s_rw[2][mm]*v; a3+=s_rw[3][mm]*v;
    }
    g_part_rw[(blockIdx.y*4+0)*WORDD+d]=a0;
    g_part_rw[(blockIdx.y*4+1)*WORDD+d]=a1;
    g_part_rw[(blockIdx.y*4+2)*WORDD+d]=a2;
    g_part_rw[(blockIdx.y*4+3)*WORDD+d]=a3;
}

// ------------- kernel 9: reduce read_words partials ------------------------
__global__ void k_rwreduce(float* __restrict__ out_rwords){
    int idx = blockIdx.x*blockDim.x+threadIdx.x; // 16384
    if (idx >= RH*WORDD) return;
    int r = idx >> 12; int d = idx & (WORDD-1);
    float s=0.f;
    #pragma unroll
    for (int t=0;t<16;t++) s += g_part_rw[(t*4+r)*WORDD+d];
    out_rwords[idx]=s;
}

// ---------------------------------------------------------------------------
extern "C" void kernel_launch(void* const* d_in, const int* in_sizes, int n_in,
                              void* d_out, int out_size) {
    const float* x      = (const float*)d_in[0];
    const float* memory = (const float*)d_in[1];
    const float* prw    = (const float*)d_in[2];
    const float* pww    = (const float*)d_in[3];
    const float* plink  = (const float*)d_in[4];
    const float* pprec  = (const float*)d_in[5];
    const float* pusage = (const float*)d_in[6];

    float* out = (float*)d_out;
    float* o_rwords = out;                            // 4*4096
    float* o_nm     = out + 16384;                    // 4096*4096
    float* o_rw     = out + 16384 + 16777216;         // 4*4096
    float* o_ww     = o_rw + 16384;                   // 2*4096
    float* o_link   = o_ww + 8192;                    // 2*4096*4096
    float* o_prec   = o_link + 33554432;              // 2*4096
    float* o_usage  = o_prec + 8192;                  // 4096

    cudaFuncSetAttribute(k_small, cudaFuncAttributeMaxDynamicSharedMemorySize, 6*MM*4);

    // side stream + events for graph-branch parallelism (capture-fork pattern)
    cudaStream_t s2;
    cudaStreamCreateWithFlags(&s2, cudaStreamNonBlocking);
    cudaEvent_t eA, eB, eS, eL;
    cudaEventCreateWithFlags(&eA, cudaEventDisableTiming);
    cudaEventCreateWithFlags(&eB, cudaEventDisableTiming);
    cudaEventCreateWithFlags(&eS, cudaEventDisableTiming);
    cudaEventCreateWithFlags(&eL, cudaEventDisableTiming);

    #define MATVEC_ARGS x, \
        (const float*)d_in[7],  (const float*)d_in[8],  \
        (const float*)d_in[9],  (const float*)d_in[10], \
        (const float*)d_in[11], (const float*)d_in[12], \
        (const float*)d_in[13], (const float*)d_in[14], \
        (const float*)d_in[15], (const float*)d_in[16], \
        (const float*)d_in[17], (const float*)d_in[18], \
        (const float*)d_in[19], (const float*)d_in[20], \
        (const float*)d_in[21], (const float*)d_in[22], \
        (const float*)d_in[23], (const float*)d_in[24], \
        (const float*)d_in[25], (const float*)d_in[26]

    // 1a. matvec phase A (wk + scalar heads) on main
    k_matvec<<<(8226*32+255)/256, 256>>>(0, MATVEC_ARGS);
    cudaEventRecord(eA, 0);
    // 1b. matvec phase B (wv/ev/rk) on s2, after A (arbitrary but keeps x reads warm)
    cudaStreamWaitEvent(s2, eA, 0);
    k_matvec<<<(32768*32+255)/256, 256, 0, s2>>>(1, MATVEC_ARGS);
    cudaEventRecord(eB, s2);
    // 2. memdot on main, overlaps matvec B
    k_memdot<<<128, 1024>>>(memory);
    // 3. serial core on main
    k_small<<<1, 1024, 6*MM*4>>>(prw, pww, pprec, pusage, o_ww, o_prec, o_usage);
    cudaEventRecord(eS, 0);
    // 5. link on s2 (needs g_ww from small; matvecB already ordered on s2)
    cudaStreamWaitEvent(s2, eS, 0);
    k_link<<<dim3(LNCH,2), 1024, 0, s2>>>(plink, pprec, prw, o_link);
    cudaEventRecord(eL, s2);
    // 4. newmem on main (needs matvec B outputs), overlaps link
    cudaStreamWaitEvent(0, eB, 0);
    k_newmem<<<128, 1024>>>(memory, o_nm);
    // join: main waits for link
    cudaStreamWaitEvent(0, eL, 0);
    // 6. bwd partial reduce
    k_bwdreduce<<<128, 256>>>();
    // 7. read weights
    k_readw<<<1, 1024>>>(o_rw);
    // 8-9. read words
    k_readwords<<<dim3(16,16), 256>>>(o_nm);
    k_rwreduce<<<64, 256>>>(o_rwords);
    #undef MATVEC_ARGS
}

// round 8
// speedup vs baseline: 1.1421x; 1.1393x over previous
#include <cuda_runtime.h>
#include <math.h>

#define MM 4096
#define WORDD 4096
#define NWH 2
#define RH 4
#define EPSV 0.001f
#define LCHUNK 32
#define LNCH 128   // 4096 / LCHUNK

// ---------------- scratch (device globals; allocation-free) ----------------
__device__ __align__(16) float g_wv[NWH*WORDD];
__device__ __align__(16) float g_ev[NWH*WORDD];
__device__ __align__(16) float g_wk[NWH*WORDD];
__device__ __align__(16) float g_rk[RH*WORDD];
__device__ __align__(16) float g_small[64]; // fg[0..3] ag[4..5] wg[6..7] rm[8..27] ws[28..29] rs[30..33]
__device__ __align__(16) float g_dot[NWH*MM];
__device__ __align__(16) float g_memnorm[MM];
__device__ __align__(16) float g_ww[NWH*MM];
__device__ __align__(16) float g_rdot[RH*MM];
__device__ __align__(16) float g_newnorm[MM];
__device__ __align__(16) float g_fwd[RH*NWH*MM];
__device__ __align__(16) float g_bwd[RH*NWH*MM];
__device__ __align__(16) float g_rw[RH*MM];
__device__ __align__(16) float g_part_bwd[NWH*LNCH*RH*MM];  // 16 MB fixed-order partials
__device__ __align__(16) float g_part_rw[16*RH*WORDD];      // 1 MB

__device__ __forceinline__ float wred(float v){
    #pragma unroll
    for (int o=16;o;o>>=1) v += __shfl_xor_sync(0xFFFFFFFFu,v,o);
    return v;
}
// grouped 4-value reduce: 6 shfls. lanes 0-7 sum(a), 8-15 sum(b), 16-23 sum(c), 24-31 sum(d)
__device__ __forceinline__ float gred4(float a, float b, float c, float d, int lane){
    float x1 = (lane&16)? a : c;
    float x2 = (lane&16)? b : d;
    float r1 = __shfl_xor_sync(0xFFFFFFFFu, x1, 16);
    float r2 = __shfl_xor_sync(0xFFFFFFFFu, x2, 16);
    float va = ((lane&16)? c : a) + r1;
    float vb = ((lane&16)? d : b) + r2;
    float y = (lane&8)? va : vb;
    float r = __shfl_xor_sync(0xFFFFFFFFu, y, 8);
    float v = ((lane&8)? vb : va) + r;
    #pragma unroll
    for (int o=4;o;o>>=1) v += __shfl_xor_sync(0xFFFFFFFFu, v, o);
    return v;
}
// grouped 2-value reduce: 6 shfls. lanes 0-15 sum(a), 16-31 sum(b)
__device__ __forceinline__ float gred2(float a, float b, int lane){
    float x = (lane&16)? a : b;
    float r = __shfl_xor_sync(0xFFFFFFFFu, x, 16);
    float v = ((lane&16)? b : a) + r;
    #pragma unroll
    for (int o=8;o;o>>=1) v += __shfl_xor_sync(0xFFFFFFFFu, v, o);
    return v;
}

// ---- bitonic helpers (packed (u,idx) uint64; keys unique => strict compares)
__device__ __forceinline__ void csw(unsigned long long& a, unsigned long long& b, bool asc){
    if (asc ? (a>b) : (a<b)){ unsigned long long t=a; a=b; b=t; }
}
// one bitonic exchange at distance j (<=64) on a warp-local 128-elem tile.
// base = first element index owned by this thread (128*warp + 4*lane).
__device__ __forceinline__ void reg_pass(unsigned long long v[4], int k, int j, int lane, int base){
    if (j>=4){
        int plane = j>>2;
        bool isLow = ((lane & plane)==0);
        bool asc = ((base & k)==0);
        bool sel = (isLow==asc);      // take partner if (mine>partner)==sel
        #pragma unroll
        for (int c=0;c<4;c++){
            unsigned long long o = __shfl_xor_sync(0xFFFFFFFFu, v[c], plane);
            bool take = sel ? (v[c]>o) : (v[c]<o);
            if (take) v[c]=o;
        }
    } else if (j==2){
        bool asc = ((base & k)==0);
        csw(v[0],v[2],asc); csw(v[1],v[3],asc);
    } else { // j==1
        if (k==2){ csw(v[0],v[1],true); csw(v[2],v[3],false); }
        else { bool asc = ((base & k)==0); csw(v[0],v[1],asc); csw(v[2],v[3],asc); }
    }
}

// ---------------- kernel 1: all linear layers (warp-per-row matvec) --------
__global__ void k_matvec(const float* __restrict__ x,
    const float* __restrict__ Wwv, const float* __restrict__ bwv,
    const float* __restrict__ Wev, const float* __restrict__ bev,
    const float* __restrict__ Wfg, const float* __restrict__ bfg,
    const float* __restrict__ Wag, const float* __restrict__ bag,
    const float* __restrict__ Wwg, const float* __restrict__ bwg,
    const float* __restrict__ Wrm, const float* __restrict__ brm,
    const float* __restrict__ Wwk, const float* __restrict__ bwk,
    const float* __restrict__ Wws, const float* __restrict__ bws,
    const float* __restrict__ Wrk, const float* __restrict__ brk,
    const float* __restrict__ Wrs, const float* __restrict__ brs)
{
    int warp = (blockIdx.x*blockDim.x + threadIdx.x) >> 5;
    int lane = threadIdx.x & 31;
    if (warp >= 40994) return;
    const float* W; const float* b; float* out; int row; int act;
    if (warp < 8192)       { W=Wwv; b=bwv; out=g_wv; row=warp;       act=0; }
    else if (warp < 16384) { W=Wev; b=bev; out=g_ev; row=warp-8192;  act=1; }
    else if (warp < 24576) { W=Wwk; b=bwk; out=g_wk; row=warp-16384; act=1; }
    else if (warp < 40960) { W=Wrk; b=brk; out=g_rk; row=warp-24576; act=0; }
    else {
        int r = warp - 40960;
        if (r < 4)       { W=Wfg; b=bfg; out=g_small+0;  row=r;    act=1; }
        else if (r < 6)  { W=Wag; b=bag; out=g_small+4;  row=r-4;  act=1; }
        else if (r < 8)  { W=Wwg; b=bwg; out=g_small+6;  row=r-6;  act=1; }
        else if (r < 28) { W=Wrm; b=brm; out=g_small+8;  row=r-8;  act=1; }
        else if (r < 30) { W=Wws; b=bws; out=g_small+28; row=r-28; act=0; }
        else             { W=Wrs; b=brs; out=g_small+30; row=r-30; act=0; }
    }
    const float4* Wr = (const float4*)(W + (size_t)row*1024);
    const float4* x4 = (const float4*)x;
    float s = 0.f;
    #pragma unroll 8
    for (int i = lane; i < 256; i += 32) {
        float4 w4 = Wr[i], xx = x4[i];
        s += w4.x*xx.x + w4.y*xx.y + w4.z*xx.z + w4.w*xx.w;
    }
    s = wred(s);
    if (lane==0) {
        s += b[row];
        if (act) s = 1.f/(1.f+expf(-s));
        out[row] = s;
    }
}

// ------------- kernel 2: dot(write_keys, memory) + memory row norms --------
__global__ void __launch_bounds__(1024) k_memdot(const float* __restrict__ memory) {
    __shared__ float s_part[32][3*32];
    int tid = threadIdx.x, lane = tid&31, wid = tid>>5;
    const float4* wk4 = (const float4*)g_wk;
    float4 k0 = __ldg(&wk4[tid]);
    float4 k1 = __ldg(&wk4[1024+tid]);
    int base = blockIdx.x*32;
    float4 vA_n = __ldg((const float4*)(memory + (size_t)base*WORDD) + tid);
    float4 vB_n = __ldg((const float4*)(memory + (size_t)(base+1)*WORDD) + tid);
    #pragma unroll 1
    for (int ii = 0; ii < 32; ii += 2) {
        float4 vA = vA_n, vB = vB_n;
        if (ii < 30) {
            vA_n = __ldg((const float4*)(memory + (size_t)(base+ii+2)*WORDD) + tid);
            vB_n = __ldg((const float4*)(memory + (size_t)(base+ii+3)*WORDD) + tid);
        }
        float dA0 = vA.x*k0.x+vA.y*k0.y+vA.z*k0.z+vA.w*k0.w;
        float dA1 = vA.x*k1.x+vA.y*k1.y+vA.z*k1.z+vA.w*k1.w;
        float nnA = vA.x*vA.x+vA.y*vA.y+vA.z*vA.z+vA.w*vA.w;
        float dB0 = vB.x*k0.x+vB.y*k0.y+vB.z*k0.z+vB.w*k0.w;
        float dB1 = vB.x*k1.x+vB.y*k1.y+vB.z*k1.z+vB.w*k1.w;
        float nnB = vB.x*vB.x+vB.y*vB.y+vB.z*vB.z+vB.w*vB.w;
        float dv = gred4(dA0,dA1,dB0,dB1,lane);
        float nv = gred2(nnA,nnB,lane);
        if (lane==0)  s_part[ii][wid]      = dv;
        if (lane==8)  s_part[ii][32+wid]   = dv;
        if (lane==16) s_part[ii+1][wid]    = dv;
        if (lane==24) s_part[ii+1][32+wid] = dv;
        if (lane==0)  s_part[ii][64+wid]   = nv;
        if (lane==16) s_part[ii+1][64+wid] = nv;
    }
    __syncthreads();
    if (tid < 96) {
        int row = tid/3, q = tid - row*3;
        float s = 0.f;
        #pragma unroll
        for (int k=0;k<32;k++) s += s_part[row][q*32+k];
        int m = base + row;
        if (q==0) g_dot[m]=s; else if (q==1) g_dot[MM+m]=s; else g_memnorm[m]=sqrtf(s);
    }
}

// ------------- kernel 3: serial core (usage, allocation sort, ww, prec) ----
__global__ void k_small(const float* __restrict__ prev_rw,
                        const float* __restrict__ prev_ww,
                        const float* __restrict__ prev_prec,
                        const float* __restrict__ prev_usage,
                        float* __restrict__ out_ww,
                        float* __restrict__ out_prec,
                        float* __restrict__ out_usage)
{
    extern __shared__ float sm[];
    float* s_usage = sm;                 // M
    float* s_a     = sm + MM;            // M
    float* s_cw    = sm + 2*MM;          // M
    unsigned long long* s_pack = (unsigned long long*)(sm + 4*MM); // M x 8B
    __shared__ float red[32];
    __shared__ float s_wsum2[32];
    __shared__ float s_wpre[32];
    __shared__ float s_bc;
    const int T = 1024;
    int tid = threadIdx.x; int lane = tid&31, wid = tid>>5;

    float fg0=g_small[0],fg1=g_small[1],fg2=g_small[2],fg3=g_small[3];

    for (int m=tid;m<MM;m+=T){
        float u = prev_usage[m];
        u = u + (1.f-u)*(1.f - prev_ww[m]*prev_ww[MM+m]);
        float p = (fg0*prev_rw[m])*(fg1*prev_rw[MM+m])*(fg2*prev_rw[2*MM+m])*(fg3*prev_rw[3*MM+m]);
        s_usage[m] = u*(1.f - p);
    }
    __syncthreads();

    for (int head=0; head<NWH; head++) {
        float kn = 0.f;
        for (int d=tid; d<WORDD; d+=T){ float k = g_wk[head*WORDD+d]; kn += k*k; }
        kn = wred(kn);
        if (lane==0) red[wid]=kn;
        __syncthreads();
        if (tid==0){ float s=0; for(int k=0;k<32;k++) s+=red[k]; s_bc = sqrtf(s);}
        __syncthreads();
        kn = s_bc;
        float ws = g_small[28+head];
        float beta = 1.f + log1pf(expf(ws));

        float mx = -3.4e38f;
        for (int m=tid;m<MM;m+=T){
            float l = g_dot[head*MM+m]/(kn*g_memnorm[m]+EPSV)*beta;
            mx = fmaxf(mx,l);
        }
        #pragma unroll
        for (int o=16;o;o>>=1) mx = fmaxf(mx,__shfl_xor_sync(0xFFFFFFFFu,mx,o));
        if (lane==0) red[wid]=mx;
        __syncthreads();
        if (tid==0){ float s=-3.4e38f; for(int k=0;k<32;k++) s=fmaxf(s,red[k]); s_bc=s;}
        __syncthreads();
        mx = s_bc;
        float sume=0.f;
        for (int m=tid;m<MM;m+=T){
            float l = g_dot[head*MM+m]/(kn*g_memnorm[m]+EPSV)*beta;
            float e = expf(l-mx);
            s_cw[m]=e; sume+=e;
        }
        sume = wred(sume);
        if (lane==0) red[wid]=sume;
        __syncthreads();
        if (tid==0){ float s=0; for(int k=0;k<32;k++) s+=red[k]; s_bc=s;}
        __syncthreads();
        float inv = 1.f/s_bc;
        for (int m=tid;m<MM;m+=T) s_cw[m] *= inv;

        // ---- stable ascending argsort: hybrid bitonic ----
        // warp w owns elements [128w,128w+128); lane holds 4 consecutive.
        {
            int base = (wid<<7) + (lane<<2);
            unsigned long long v[4];
            #pragma unroll
            for (int c=0;c<4;c++){
                int m = base+c;
                float u = EPSV + (1.f-EPSV)*s_usage[m];
                v[c] = ((unsigned long long)__float_as_uint(u) << 32) | (unsigned)m;
            }
            // k = 2..128: entirely warp-local, zero barriers
            #pragma unroll
            for (int k=2;k<=128;k<<=1)
                for (int j=k>>1;j>0;j>>=1) reg_pass(v,k,j,lane,base);
            #pragma unroll
            for (int c=0;c<4;c++) s_pack[base+c]=v[c];
            __syncthreads();
            // k = 256..4096: smem passes for j>=128, warp-local for j<=64
            for (int k=256;k<=MM;k<<=1){
                for (int j=k>>1;j>=128;j>>=1){
                    for (int p=tid;p<MM/2;p+=T){
                        int t = ((p & ~(j-1))<<1) | (p & (j-1));
                        int l2 = t + j;
                        unsigned long long a=s_pack[t], b=s_pack[l2];
                        bool asc = ((t & k)==0);
                        if (asc ? (a>b) : (a<b)){ s_pack[t]=b; s_pack[l2]=a; }
                    }
                    __syncthreads();
                }
                #pragma unroll
                for (int c=0;c<4;c++) v[c]=s_pack[base+c];
                for (int j=64;j>0;j>>=1) reg_pass(v,k,j,lane,base);
                #pragma unroll
                for (int c=0;c<4;c++) s_pack[base+c]=v[c];
                __syncthreads();
            }
        }

        // cumprod scan + alloc scatter
        {
            int base = tid*4;
            unsigned long long p0=s_pack[base],p1=s_pack[base+1],p2=s_pack[base+2],p3=s_pack[base+3];
            float x0=__uint_as_float((unsigned)(p0>>32));
            float x1=__uint_as_float((unsigned)(p1>>32));
            float x2=__uint_as_float((unsigned)(p2>>32));
            float x3=__uint_as_float((unsigned)(p3>>32));
            float c0=x0, c1=c0*x1, c2=c1*x2, c3=c2*x3;
            float t3=c3;
            #pragma unroll
            for (int o=1;o<32;o<<=1){ float n=__shfl_up_sync(0xFFFFFFFFu,t3,o); if (lane>=o) t3*=n; }
            float warpExcl = __shfl_up_sync(0xFFFFFFFFu,t3,1); if (lane==0) warpExcl=1.f;
            if (lane==31) s_wsum2[wid]=t3;
            __syncthreads();
            if (tid<32){
                float w = s_wsum2[tid];
                float tw=w;
                #pragma unroll
                for (int o=1;o<32;o<<=1){ float n=__shfl_up_sync(0xFFFFFFFFu,tw,o); if (tid>=o) tw*=n; }
                float excl = __shfl_up_sync(0xFFFFFFFFu,tw,1); if (tid==0) excl=1.f;
                s_wpre[tid]=excl;
            }
            __syncthreads();
            float pre = s_wpre[wid]*warpExcl;
            int i0=(int)(p0&0xFFFFFFFFull), i1=(int)(p1&0xFFFFFFFFull);
            int i2=(int)(p2&0xFFFFFFFFull), i3=(int)(p3&0xFFFFFFFFull);
            s_a[i0]=(1.f-x0)*pre;
            s_a[i1]=(1.f-x1)*pre*c0;
            s_a[i2]=(1.f-x2)*pre*c1;
            s_a[i3]=(1.f-x3)*pre*c2;
            __syncthreads();
        }

        float ag = g_small[4+head], wg = g_small[6+head];
        float wsum = 0.f;
        for (int m=tid;m<MM;m+=T){
            float a = s_a[m];
            float cw = s_cw[m];
            float w = wg*(ag*a + (1.f-ag)*cw);
            g_ww[head*MM+m] = w;
            out_ww[head*MM+m] = w;
            wsum += w;
            float u = s_usage[m];
            s_usage[m] = u + (1.f - u)*(ag*wg)*a;
        }
        wsum = wred(wsum);
        if (lane==0) red[wid]=wsum;
        __syncthreads();
        if (tid==0){ float s=0; for(int k=0;k<32;k++) s+=red[k]; s_bc=s;}
        __syncthreads();
        float oms = 1.f - s_bc;
        for (int m=tid;m<MM;m+=T)
            out_prec[head*MM+m] = oms*prev_prec[head*MM+m] + g_ww[head*MM+m];
        __syncthreads();
    }
    for (int m=tid;m<MM;m+=T) out_usage[m]=s_usage[m];
}

// ------------- kernel 4: new_memory + fused rdot + new norms ---------------
__global__ void __launch_bounds__(1024) k_newmem(const float* __restrict__ memory,
                                                 float* __restrict__ out_nm){
    __shared__ float s_part[32][5*32];
    int tid=threadIdx.x, lane=tid&31, wid=tid>>5;
    const float4* ev4=(const float4*)g_ev;
    const float4* wv4=(const float4*)g_wv;
    const float4* rk4=(const float4*)g_rk;
    float4 e0=__ldg(&ev4[tid]),      e1=__ldg(&ev4[1024+tid]);
    float4 a0=__ldg(&wv4[tid]),      a1=__ldg(&wv4[1024+tid]);
    float4 k0=__ldg(&rk4[tid]),      k1=__ldg(&rk4[1024+tid]);
    float4 k2=__ldg(&rk4[2048+tid]), k3=__ldg(&rk4[3072+tid]);
    int base = blockIdx.x*32;
    float4 v_next = __ldg((const float4*)(memory+(size_t)base*WORDD) + tid);
    #pragma unroll 1
    for (int ii=0; ii<32; ii++){
        int m = base+ii;
        float4 v = v_next;
        if (ii<31) v_next = __ldg((const float4*)(memory+(size_t)(m+1)*WORDD) + tid);
        float w0=__ldg(&g_ww[m]), w1=__ldg(&g_ww[MM+m]);
        float4 o;
        o.x = v.x*((1.f-w0*e0.x)*(1.f-w1*e1.x)) + w0*a0.x + w1*a1.x;
        o.y = v.y*((1.f-w0*e0.y)*(1.f-w1*e1.y)) + w0*a0.y + w1*a1.y;
        o.z = v.z*((1.f-w0*e0.z)*(1.f-w1*e1.z)) + w0*a0.z + w1*a1.z;
        o.w = v.w*((1.f-w0*e0.w)*(1.f-w1*e1.w)) + w0*a0.w + w1*a1.w;
        ((float4*)(out_nm+(size_t)m*WORDD))[tid]=o;
        float r0 = o.x*k0.x+o.y*k0.y+o.z*k0.z+o.w*k0.w;
        float r1 = o.x*k1.x+o.y*k1.y+o.z*k1.z+o.w*k1.w;
        float r2 = o.x*k2.x+o.y*k2.y+o.z*k2.z+o.w*k2.w;
        float r3 = o.x*k3.x+o.y*k3.y+o.z*k3.z+o.w*k3.w;
        float nn = o.x*o.x+o.y*o.y+o.z*o.z+o.w*o.w;
        float rv = gred4(r0,r1,r2,r3,lane);
        float nv = wred(nn);
        if ((lane&7)==0) s_part[ii][(lane>>3)*32+wid] = rv;
        if (lane==0)     s_part[ii][128+wid] = nv;
    }
    __syncthreads();
    if (tid < 160){
        int row=tid/5, q=tid-row*5;
        float s=0.f;
        #pragma unroll
        for (int k=0;k<32;k++) s += s_part[row][q*32+k];
        int m = base + row;
        if (q<4) g_rdot[q*MM+m]=s; else g_newnorm[m]=sqrtf(s);
    }
}

// ------------- kernel 5: link update + fused fwd_w/bwd_w -------------------
// 512 threads, 2 float4 columns/thread (no reg cap -> no spills), row prefetch
__global__ void __launch_bounds__(512) k_link(const float* __restrict__ prev_link,
                       const float* __restrict__ prev_prec,
                       const float* __restrict__ prev_rw,
                       float* __restrict__ out_link){
    __shared__ float s_fred[LCHUNK][4][16];
    int w = blockIdx.y;
    int chunk = blockIdx.x;
    int i0 = chunk*LCHUNK;
    int tid=threadIdx.x, lane=tid&31, wid=tid>>5;
    const float4* ww4 = (const float4*)(g_ww + w*MM);
    const float4* pp4 = (const float4*)(prev_prec + w*MM);
    const float4* pr4 = (const float4*)prev_rw;
    float4 wwa=__ldg(&ww4[tid]),       wwb=__ldg(&ww4[512+tid]);
    float4 ppa=__ldg(&pp4[tid]),       ppb=__ldg(&pp4[512+tid]);
    float4 pa0=__ldg(&pr4[tid]),       pb0=__ldg(&pr4[512+tid]);
    float4 pa1=__ldg(&pr4[1024+tid]),  pb1=__ldg(&pr4[1536+tid]);
    float4 pa2=__ldg(&pr4[2048+tid]),  pb2=__ldg(&pr4[2560+tid]);
    float4 pa3=__ldg(&pr4[3072+tid]),  pb3=__ldg(&pr4[3584+tid]);
    float bw0[8],bw1[8],bw2[8],bw3[8];
    #pragma unroll
    for (int c=0;c<8;c++){ bw0[c]=0.f;bw1[c]=0.f;bw2[c]=0.f;bw3[c]=0.f; }
    int ja = tid*4, jb = (512+tid)*4;
    const float4* plbase = (const float4*)(prev_link + (size_t)w*MM*MM);
    float4 pA_n = __ldcs(plbase + (size_t)i0*1024 + tid);
    float4 pB_n = __ldcs(plbase + (size_t)i0*1024 + 512 + tid);
    #pragma unroll 1
    for (int ii=0; ii<LCHUNK; ii++){
        int i = i0+ii;
        float4 pA = pA_n, pB = pB_n;
        if (ii<LCHUNK-1){
            pA_n = __ldcs(plbase + (size_t)(i+1)*1024 + tid);
            pB_n = __ldcs(plbase + (size_t)(i+1)*1024 + 512 + tid);
        }
        float wwi = __ldg(&g_ww[w*MM+i]);
        float pri0=__ldg(&prev_rw[i]),      pri1=__ldg(&prev_rw[MM+i]);
        float pri2=__ldg(&prev_rw[2*MM+i]), pri3=__ldg(&prev_rw[3*MM+i]);
        float f0=0.f,f1=0.f,f2=0.f,f3=0.f;
        float4 oA, oB;
        {
            float l = (1.f-wwi-wwa.x)*pA.x + wwi*ppa.x; if (ja+0==i) l=0.f; oA.x=l;
            f0+=pa0.x*l; f1+=pa1.x*l; f2+=pa2.x*l; f3+=pa3.x*l;
            bw0[0]+=pri0*l; bw1[0]+=pri1*l; bw2[0]+=pri2*l; bw3[0]+=pri3*l;
        }
        {
            float l = (1.f-wwi-wwa.y)*pA.y + wwi*ppa.y; if (ja+1==i) l=0.f; oA.y=l;
            f0+=pa0.y*l; f1+=pa1.y*l; f2+=pa2.y*l; f3+=pa3.y*l;
            bw0[1]+=pri0*l; bw1[1]+=pri1*l; bw2[1]+=pri2*l; bw3[1]+=pri3*l;
        }
        {
            float l = (1.f-wwi-wwa.z)*pA.z + wwi*ppa.z; if (ja+2==i) l=0.f; oA.z=l;
            f0+=pa0.z*l; f1+=pa1.z*l; f2+=pa2.z*l; f3+=pa3.z*l;
            bw0[2]+=pri0*l; bw1[2]+=pri1*l; bw2[2]+=pri2*l; bw3[2]+=pri3*l;
        }
        {
            float l = (1.f-wwi-wwa.w)*pA.w + wwi*ppa.w; if (ja+3==i) l=0.f; oA.w=l;
            f0+=pa0.w*l; f1+=pa1.w*l; f2+=pa2.w*l; f3+=pa3.w*l;
            bw0[3]+=pri0*l; bw1[3]+=pri1*l; bw2[3]+=pri2*l; bw3[3]+=pri3*l;
        }
        {
            float l = (1.f-wwi-wwb.x)*pB.x + wwi*ppb.x; if (jb+0==i) l=0.f; oB.x=l;
            f0+=pb0.x*l; f1+=pb1.x*l; f2+=pb2.x*l; f3+=pb3.x*l;
            bw0[4]+=pri0*l; bw1[4]+=pri1*l; bw2[4]+=pri2*l; bw3[4]+=pri3*l;
        }
        {
            float l = (1.f-wwi-wwb.y)*pB.y + wwi*ppb.y; if (jb+1==i) l=0.f; oB.y=l;
            f0+=pb0.y*l; f1+=pb1.y*l; f2+=pb2.y*l; f3+=pb3.y*l;
            bw0[5]+=pri0*l; bw1[5]+=pri1*l; bw2[5]+=pri2*l; bw3[5]+=pri3*l;
        }
        {
            float l = (1.f-wwi-wwb.z)*pB.z + wwi*ppb.z; if (jb+2==i) l=0.f; oB.z=l;
            f0+=pb0.z*l; f1+=pb1.z*l; f2+=pb2.z*l; f3+=pb3.z*l;
            bw0[6]+=pri0*l; bw1[6]+=pri1*l; bw2[6]+=pri2*l; bw3[6]+=pri3*l;
        }
        {
            float l = (1.f-wwi-wwb.w)*pB.w + wwi*ppb.w; if (jb+3==i) l=0.f; oB.w=l;
            f0+=pb0.w*l; f1+=pb1.w*l; f2+=pb2.w*l; f3+=pb3.w*l;
            bw0[7]+=pri0*l; bw1[7]+=pri1*l; bw2[7]+=pri2*l; bw3[7]+=pri3*l;
        }
        float4* lo = (float4*)(out_link + ((size_t)w*MM+i)*MM);
        __stcs(lo + tid, oA);
        __stcs(lo + 512 + tid, oB);
        float fv = gred4(f0,f1,f2,f3,lane);
        if ((lane&7)==0) s_fred[ii][lane>>3][wid]=fv;
    }
    __syncthreads();
    if (tid < LCHUNK*4){
        int row = tid>>2, r = tid&3;
        float s=0.f;
        #pragma unroll
        for (int k=0;k<16;k++) s += s_fred[row][r][k];
        g_fwd[(r*NWH + w)*MM + i0 + row] = s;
    }
    size_t pb = (size_t)(w*LNCH + chunk)*4;
    ((float4*)(g_part_bwd + (pb+0)*MM))[tid]     = make_float4(bw0[0],bw0[1],bw0[2],bw0[3]);
    ((float4*)(g_part_bwd + (pb+0)*MM))[512+tid] = make_float4(bw0[4],bw0[5],bw0[6],bw0[7]);
    ((float4*)(g_part_bwd + (pb+1)*MM))[tid]     = make_float4(bw1[0],bw1[1],bw1[2],bw1[3]);
    ((float4*)(g_part_bwd + (pb+1)*MM))[512+tid] = make_float4(bw1[4],bw1[5],bw1[6],bw1[7]);
    ((float4*)(g_part_bwd + (pb+2)*MM))[tid]     = make_float4(bw2[0],bw2[1],bw2[2],bw2[3]);
    ((float4*)(g_part_bwd + (pb+2)*MM))[512+tid] = make_float4(bw2[4],bw2[5],bw2[6],bw2[7]);
    ((float4*)(g_part_bwd + (pb+3)*MM))[tid]     = make_float4(bw3[0],bw3[1],bw3[2],bw3[3]);
    ((float4*)(g_part_bwd + (pb+3)*MM))[512+tid] = make_float4(bw3[4],bw3[5],bw3[6],bw3[7]);
}

// ------------- kernel 6: reduce bwd partials (fixed order, deterministic) --
__global__ void k_bwdreduce(){
    int idx = blockIdx.x*blockDim.x + threadIdx.x; // 32768
    if (idx >= RH*NWH*MM) return;
    int m = idx & (MM-1);
    int w = (idx >> 12) & 1;
    int r = idx >> 13;
    float s=0.f;
    #pragma unroll 8
    for (int t=0;t<LNCH;t++)
        s += g_part_bwd[((size_t)(w*LNCH+t)*4 + r)*MM + m];
    g_bwd[idx]=s;
}

// ------------- kernel 7: read weights (content softmax + mode combine) -----
__global__ void k_readw(float* __restrict__ out_rw){
    __shared__ float s_e[MM];
    __shared__ float red[32];
    __shared__ float s_bc;
    const int T = 1024;
    int tid=threadIdx.x, lane=tid&31, wid=tid>>5;
    for (int r=0;r<RH;r++){
        float kn=0.f;
        for (int d=tid;d<WORDD;d+=T){ float k=g_rk[r*WORDD+d]; kn+=k*k; }
        kn = wred(kn);
        if (lane==0) red[wid]=kn;
        __syncthreads();
        if (tid==0){ float s=0; for(int k=0;k<32;k++) s+=red[k]; s_bc=sqrtf(s);}
        __syncthreads();
        kn=s_bc;
        float rs = g_small[30+r];
        float mx=-3.4e38f;
        for (int m=tid;m<MM;m+=T){
            float l = g_rdot[r*MM+m]/(kn*g_newnorm[m])*rs;
            mx=fmaxf(mx,l);
        }
        #pragma unroll
        for (int o=16;o;o>>=1) mx=fmaxf(mx,__shfl_xor_sync(0xFFFFFFFFu,mx,o));
        if (lane==0) red[wid]=mx;
        __syncthreads();
        if (tid==0){ float s=-3.4e38f; for(int k=0;k<32;k++) s=fmaxf(s,red[k]); s_bc=s;}
        __syncthreads();
        mx=s_bc;
        float sume=0.f;
        for (int m=tid;m<MM;m+=T){
            float l = g_rdot[r*MM+m]/(kn*g_newnorm[m])*rs;
            float e = expf(l-mx);
            s_e[m]=e; sume+=e;
        }
        sume = wred(sume);
        if (lane==0) red[wid]=sume;
        __syncthreads();
        if (tid==0){ float s=0; for(int k=0;k<32;k++) s+=red[k]; s_bc=s;}
        __syncthreads();
        float inv = 1.f/s_bc;
        float bm0=g_small[8+r*5+0], bm1=g_small[8+r*5+1];
        float fm0=g_small[8+r*5+2], fm1=g_small[8+r*5+3];
        float cm =g_small[8+r*5+4];
        for (int m=tid;m<MM;m+=T){
            float v = bm0*g_bwd[(r*2+0)*MM+m] + bm1*g_bwd[(r*2+1)*MM+m]
                    + fm0*g_fwd[(r*2+0)*MM+m] + fm1*g_fwd[(r*2+1)*MM+m]
                    + cm*s_e[m]*inv;
            g_rw[r*MM+m]=v; out_rw[r*MM+m]=v;
        }
        __syncthreads();
    }
}

// ------------- kernel 8: read_words partials -------------------------------
__global__ void k_readwords(const float* __restrict__ nm){
    __shared__ float s_rw[4][256];
    int d = blockIdx.x*256 + threadIdx.x;
    int m0 = blockIdx.y*256;
    #pragma unroll
    for (int r=0;r<4;r++) s_rw[r][threadIdx.x] = g_rw[r*MM + m0 + threadIdx.x];
    __syncthreads();
    float a0=0,a1=0,a2=0,a3=0;
    #pragma unroll 4
    for (int mm=0;mm<256;mm++){
        float v = nm[(size_t)(m0+mm)*WORDD + d];
        a0+=s_rw[0][mm]*v; a1+=s_rw[1][mm]*v; a2+=s_rw[2][mm]*v; a3+=s_rw[3][mm]*v;
    }
    g_part_rw[(blockIdx.y*4+0)*WORDD+d]=a0;
    g_part_rw[(blockIdx.y*4+1)*WORDD+d]=a1;
    g_part_rw[(blockIdx.y*4+2)*WORDD+d]=a2;
    g_part_rw[(blockIdx.y*4+3)*WORDD+d]=a3;
}

// ------------- kernel 9: reduce read_words partials ------------------------
__global__ void k_rwreduce(float* __restrict__ out_rwords){
    int idx = blockIdx.x*blockDim.x+threadIdx.x; // 16384
    if (idx >= RH*WORDD) return;
    int r = idx >> 12; int d = idx & (WORDD-1);
    float s=0.f;
    #pragma unroll
    for (int t=0;t<16;t++) s += g_part_rw[(t*4+r)*WORDD+d];
    out_rwords[idx]=s;
}

// ---------------------------------------------------------------------------
extern "C" void kernel_launch(void* const* d_in, const int* in_sizes, int n_in,
                              void* d_out, int out_size) {
    const float* x      = (const float*)d_in[0];
    const float* memory = (const float*)d_in[1];
    const float* prw    = (const float*)d_in[2];
    const float* pww    = (const float*)d_in[3];
    const float* plink  = (const float*)d_in[4];
    const float* pprec  = (const float*)d_in[5];
    const float* pusage = (const float*)d_in[6];

    float* out = (float*)d_out;
    float* o_rwords = out;                            // 4*4096
    float* o_nm     = out + 16384;                    // 4096*4096
    float* o_rw     = out + 16384 + 16777216;         // 4*4096
    float* o_ww     = o_rw + 16384;                   // 2*4096
    float* o_link   = o_ww + 8192;                    // 2*4096*4096
    float* o_prec   = o_link + 33554432;              // 2*4096
    float* o_usage  = o_prec + 8192;                  // 4096

    cudaFuncSetAttribute(k_small, cudaFuncAttributeMaxDynamicSharedMemorySize, 6*MM*4);

    // 1. all linears
    {
        int warps = 40994;
        int blocks = (warps*32 + 255)/256;
        k_matvec<<<blocks, 256>>>(x,
            (const float*)d_in[7],  (const float*)d_in[8],
            (const float*)d_in[9],  (const float*)d_in[10],
            (const float*)d_in[11], (const float*)d_in[12],
            (const float*)d_in[13], (const float*)d_in[14],
            (const float*)d_in[15], (const float*)d_in[16],
            (const float*)d_in[17], (const float*)d_in[18],
            (const float*)d_in[19], (const float*)d_in[20],
            (const float*)d_in[21], (const float*)d_in[22],
            (const float*)d_in[23], (const float*)d_in[24],
            (const float*)d_in[25], (const float*)d_in[26]);
    }
    // 2. write-key similarity dot + mem norms
    k_memdot<<<128, 1024>>>(memory);
    // 3. serial core (new hybrid sort)
    k_small<<<1, 1024, 6*MM*4>>>(prw, pww, pprec, pusage, o_ww, o_prec, o_usage);
    // 4. new memory + fused rdot / norms
    k_newmem<<<128, 1024>>>(memory, o_nm);
    // 5. link + fused fwd/bwd partials (512 thr, 2 cols, no spills)
    k_link<<<dim3(LNCH,2), 512>>>(plink, pprec, prw, o_link);
    // 6. bwd partial reduce
    k_bwdreduce<<<128, 256>>>();
    // 7. read weights
    k_readw<<<1, 1024>>>(o_rw);
    // 8-9. read words
    k_readwords<<<dim3(16,16), 256>>>(o_nm);
    k_rwreduce<<<64, 256>>>(o_rwords);
}

// round 9
// speedup vs baseline: 1.2523x; 1.0965x over previous
#include <cuda_runtime.h>
#include <math.h>

#define MM 4096
#define WORDD 4096
#define NWH 2
#define RH 4
#define EPSV 0.001f
#define LCHUNK 64
#define LNCH 64   // 4096 / LCHUNK

// ---------------- scratch (device globals; allocation-free) ----------------
__device__ __align__(16) float g_wv[NWH*WORDD];
__device__ __align__(16) float g_ev[NWH*WORDD];
__device__ __align__(16) float g_wk[NWH*WORDD];
__device__ __align__(16) float g_rk[RH*WORDD];
__device__ __align__(16) float g_small[64]; // fg[0..3] ag[4..5] wg[6..7] rm[8..27] ws[28..29] rs[30..33]
__device__ __align__(16) float g_dot[NWH*MM];
__device__ __align__(16) float g_memnorm[MM];
__device__ __align__(16) float g_ww[NWH*MM];
__device__ __align__(16) float g_rdot[RH*MM];
__device__ __align__(16) float g_newnorm[MM];
__device__ __align__(16) float g_fwd[RH*NWH*MM];
__device__ __align__(16) float g_bwd[RH*NWH*MM];
__device__ __align__(16) float g_rw[RH*MM];
__device__ __align__(16) float g_part_bwd[NWH*LNCH*RH*MM];  // 8 MB fixed-order partials
__device__ __align__(16) float g_part_rw[16*RH*WORDD];      // 1 MB

__device__ __forceinline__ float wred(float v){
    #pragma unroll
    for (int o=16;o;o>>=1) v += __shfl_xor_sync(0xFFFFFFFFu,v,o);
    return v;
}
// grouped 4-value reduce: 6 shfls. lanes 0-7 sum(a), 8-15 sum(b), 16-23 sum(c), 24-31 sum(d)
__device__ __forceinline__ float gred4(float a, float b, float c, float d, int lane){
    float x1 = (lane&16)? a : c;
    float x2 = (lane&16)? b : d;
    float r1 = __shfl_xor_sync(0xFFFFFFFFu, x1, 16);
    float r2 = __shfl_xor_sync(0xFFFFFFFFu, x2, 16);
    float va = ((lane&16)? c : a) + r1;
    float vb = ((lane&16)? d : b) + r2;
    float y = (lane&8)? va : vb;
    float r = __shfl_xor_sync(0xFFFFFFFFu, y, 8);
    float v = ((lane&8)? vb : va) + r;
    #pragma unroll
    for (int o=4;o;o>>=1) v += __shfl_xor_sync(0xFFFFFFFFu, v, o);
    return v;
}
// grouped 2-value reduce: 6 shfls. lanes 0-15 sum(a), 16-31 sum(b)
__device__ __forceinline__ float gred2(float a, float b, int lane){
    float x = (lane&16)? a : b;
    float r = __shfl_xor_sync(0xFFFFFFFFu, x, 16);
    float v = ((lane&16)? b : a) + r;
    #pragma unroll
    for (int o=8;o;o>>=1) v += __shfl_xor_sync(0xFFFFFFFFu, v, o);
    return v;
}

// ---- bitonic helpers (packed (u,idx) uint64; keys unique => strict compares)
__device__ __forceinline__ void csw(unsigned long long& a, unsigned long long& b, bool asc){
    if (asc ? (a>b) : (a<b)){ unsigned long long t=a; a=b; b=t; }
}
__device__ __forceinline__ void reg_pass(unsigned long long v[4], int k, int j, int lane, int base){
    if (j>=4){
        int plane = j>>2;
        bool isLow = ((lane & plane)==0);
        bool asc = ((base & k)==0);
        bool sel = (isLow==asc);
        #pragma unroll
        for (int c=0;c<4;c++){
            unsigned long long o = __shfl_xor_sync(0xFFFFFFFFu, v[c], plane);
            bool take = sel ? (v[c]>o) : (v[c]<o);
            if (take) v[c]=o;
        }
    } else if (j==2){
        bool asc = ((base & k)==0);
        csw(v[0],v[2],asc); csw(v[1],v[3],asc);
    } else {
        if (k==2){ csw(v[0],v[1],true); csw(v[2],v[3],false); }
        else { bool asc = ((base & k)==0); csw(v[0],v[1],asc); csw(v[2],v[3],asc); }
    }
}

// ---------------- kernel 1: all linear layers (warp-per-row matvec) --------
__global__ void k_matvec(const float* __restrict__ x,
    const float* __restrict__ Wwv, const float* __restrict__ bwv,
    const float* __restrict__ Wev, const float* __restrict__ bev,
    const float* __restrict__ Wfg, const float* __restrict__ bfg,
    const float* __restrict__ Wag, const float* __restrict__ bag,
    const float* __restrict__ Wwg, const float* __restrict__ bwg,
    const float* __restrict__ Wrm, const float* __restrict__ brm,
    const float* __restrict__ Wwk, const float* __restrict__ bwk,
    const float* __restrict__ Wws, const float* __restrict__ bws,
    const float* __restrict__ Wrk, const float* __restrict__ brk,
    const float* __restrict__ Wrs, const float* __restrict__ brs)
{
    int warp = (blockIdx.x*blockDim.x + threadIdx.x) >> 5;
    int lane = threadIdx.x & 31;
    if (warp >= 40994) return;
    const float* W; const float* b; float* out; int row; int act;
    if (warp < 8192)       { W=Wwv; b=bwv; out=g_wv; row=warp;       act=0; }
    else if (warp < 16384) { W=Wev; b=bev; out=g_ev; row=warp-8192;  act=1; }
    else if (warp < 24576) { W=Wwk; b=bwk; out=g_wk; row=warp-16384; act=1; }
    else if (warp < 40960) { W=Wrk; b=brk; out=g_rk; row=warp-24576; act=0; }
    else {
        int r = warp - 40960;
        if (r < 4)       { W=Wfg; b=bfg; out=g_small+0;  row=r;    act=1; }
        else if (r < 6)  { W=Wag; b=bag; out=g_small+4;  row=r-4;  act=1; }
        else if (r < 8)  { W=Wwg; b=bwg; out=g_small+6;  row=r-6;  act=1; }
        else if (r < 28) { W=Wrm; b=brm; out=g_small+8;  row=r-8;  act=1; }
        else if (r < 30) { W=Wws; b=bws; out=g_small+28; row=r-28; act=0; }
        else             { W=Wrs; b=brs; out=g_small+30; row=r-30; act=0; }
    }
    const float4* Wr = (const float4*)(W + (size_t)row*1024);
    const float4* x4 = (const float4*)x;
    float s = 0.f;
    #pragma unroll 8
    for (int i = lane; i < 256; i += 32) {
        float4 w4 = Wr[i], xx = x4[i];
        s += w4.x*xx.x + w4.y*xx.y + w4.z*xx.z + w4.w*xx.w;
    }
    s = wred(s);
    if (lane==0) {
        s += b[row];
        if (act) s = 1.f/(1.f+expf(-s));
        out[row] = s;
    }
}

// ------------- kernel 2: dot(write_keys, memory) + memory row norms --------
__global__ void __launch_bounds__(1024) k_memdot(const float* __restrict__ memory) {
    __shared__ float s_part[32][3*32];
    int tid = threadIdx.x, lane = tid&31, wid = tid>>5;
    const float4* wk4 = (const float4*)g_wk;
    float4 k0 = __ldg(&wk4[tid]);
    float4 k1 = __ldg(&wk4[1024+tid]);
    int base = blockIdx.x*32;
    float4 vA_n = __ldg((const float4*)(memory + (size_t)base*WORDD) + tid);
    float4 vB_n = __ldg((const float4*)(memory + (size_t)(base+1)*WORDD) + tid);
    #pragma unroll 1
    for (int ii = 0; ii < 32; ii += 2) {
        float4 vA = vA_n, vB = vB_n;
        if (ii < 30) {
            vA_n = __ldg((const float4*)(memory + (size_t)(base+ii+2)*WORDD) + tid);
            vB_n = __ldg((const float4*)(memory + (size_t)(base+ii+3)*WORDD) + tid);
        }
        float dA0 = vA.x*k0.x+vA.y*k0.y+vA.z*k0.z+vA.w*k0.w;
        float dA1 = vA.x*k1.x+vA.y*k1.y+vA.z*k1.z+vA.w*k1.w;
        float nnA = vA.x*vA.x+vA.y*vA.y+vA.z*vA.z+vA.w*vA.w;
        float dB0 = vB.x*k0.x+vB.y*k0.y+vB.z*k0.z+vB.w*k0.w;
        float dB1 = vB.x*k1.x+vB.y*k1.y+vB.z*k1.z+vB.w*k1.w;
        float nnB = vB.x*vB.x+vB.y*vB.y+vB.z*vB.z+vB.w*vB.w;
        float dv = gred4(dA0,dA1,dB0,dB1,lane);
        float nv = gred2(nnA,nnB,lane);
        if (lane==0)  s_part[ii][wid]      = dv;
        if (lane==8)  s_part[ii][32+wid]   = dv;
        if (lane==16) s_part[ii+1][wid]    = dv;
        if (lane==24) s_part[ii+1][32+wid] = dv;
        if (lane==0)  s_part[ii][64+wid]   = nv;
        if (lane==16) s_part[ii+1][64+wid] = nv;
    }
    __syncthreads();
    if (tid < 96) {
        int row = tid/3, q = tid - row*3;
        float s = 0.f;
        #pragma unroll
        for (int k=0;k<32;k++) s += s_part[row][q*32+k];
        int m = base + row;
        if (q==0) g_dot[m]=s; else if (q==1) g_dot[MM+m]=s; else g_memnorm[m]=sqrtf(s);
    }
}

// ------------- kernel 3: serial core (usage, allocation sort, ww, prec) ----
__global__ void k_small(const float* __restrict__ prev_rw,
                        const float* __restrict__ prev_ww,
                        const float* __restrict__ prev_prec,
                        const float* __restrict__ prev_usage,
                        float* __restrict__ out_ww,
                        float* __restrict__ out_prec,
                        float* __restrict__ out_usage)
{
    extern __shared__ float sm[];
    float* s_usage = sm;                 // M
    float* s_a     = sm + MM;            // M
    float* s_cw    = sm + 2*MM;          // M
    unsigned long long* s_pack = (unsigned long long*)(sm + 4*MM); // M x 8B
    __shared__ float red[32];
    __shared__ float s_wsum2[32];
    __shared__ float s_wpre[32];
    __shared__ float s_bc;
    const int T = 1024;
    int tid = threadIdx.x; int lane = tid&31, wid = tid>>5;

    float fg0=g_small[0],fg1=g_small[1],fg2=g_small[2],fg3=g_small[3];

    for (int m=tid;m<MM;m+=T){
        float u = prev_usage[m];
        u = u + (1.f-u)*(1.f - prev_ww[m]*prev_ww[MM+m]);
        float p = (fg0*prev_rw[m])*(fg1*prev_rw[MM+m])*(fg2*prev_rw[2*MM+m])*(fg3*prev_rw[3*MM+m]);
        s_usage[m] = u*(1.f - p);
    }
    __syncthreads();

    for (int head=0; head<NWH; head++) {
        float kn = 0.f;
        for (int d=tid; d<WORDD; d+=T){ float k = g_wk[head*WORDD+d]; kn += k*k; }
        kn = wred(kn);
        if (lane==0) red[wid]=kn;
        __syncthreads();
        if (tid==0){ float s=0; for(int k=0;k<32;k++) s+=red[k]; s_bc = sqrtf(s);}
        __syncthreads();
        kn = s_bc;
        float ws = g_small[28+head];
        float beta = 1.f + log1pf(expf(ws));

        float mx = -3.4e38f;
        for (int m=tid;m<MM;m+=T){
            float l = g_dot[head*MM+m]/(kn*g_memnorm[m]+EPSV)*beta;
            mx = fmaxf(mx,l);
        }
        #pragma unroll
        for (int o=16;o;o>>=1) mx = fmaxf(mx,__shfl_xor_sync(0xFFFFFFFFu,mx,o));
        if (lane==0) red[wid]=mx;
        __syncthreads();
        if (tid==0){ float s=-3.4e38f; for(int k=0;k<32;k++) s=fmaxf(s,red[k]); s_bc=s;}
        __syncthreads();
        mx = s_bc;
        float sume=0.f;
        for (int m=tid;m<MM;m+=T){
            float l = g_dot[head*MM+m]/(kn*g_memnorm[m]+EPSV)*beta;
            float e = expf(l-mx);
            s_cw[m]=e; sume+=e;
        }
        sume = wred(sume);
        if (lane==0) red[wid]=sume;
        __syncthreads();
        if (tid==0){ float s=0; for(int k=0;k<32;k++) s+=red[k]; s_bc=s;}
        __syncthreads();
        float inv = 1.f/s_bc;
        for (int m=tid;m<MM;m+=T) s_cw[m] *= inv;

        // ---- stable ascending argsort: hybrid bitonic ----
        {
            int base = (wid<<7) + (lane<<2);
            unsigned long long v[4];
            #pragma unroll
            for (int c=0;c<4;c++){
                int m = base+c;
                float u = EPSV + (1.f-EPSV)*s_usage[m];
                v[c] = ((unsigned long long)__float_as_uint(u) << 32) | (unsigned)m;
            }
            #pragma unroll
            for (int k=2;k<=128;k<<=1)
                for (int j=k>>1;j>0;j>>=1) reg_pass(v,k,j,lane,base);
            #pragma unroll
            for (int c=0;c<4;c++) s_pack[base+c]=v[c];
            __syncthreads();
            for (int k=256;k<=MM;k<<=1){
                for (int j=k>>1;j>=128;j>>=1){
                    for (int p=tid;p<MM/2;p+=T){
                        int t = ((p & ~(j-1))<<1) | (p & (j-1));
                        int l2 = t + j;
                        unsigned long long a=s_pack[t], b=s_pack[l2];
                        bool asc = ((t & k)==0);
                        if (asc ? (a>b) : (a<b)){ s_pack[t]=b; s_pack[l2]=a; }
                    }
                    __syncthreads();
                }
                #pragma unroll
                for (int c=0;c<4;c++) v[c]=s_pack[base+c];
                for (int j=64;j>0;j>>=1) reg_pass(v,k,j,lane,base);
                #pragma unroll
                for (int c=0;c<4;c++) s_pack[base+c]=v[c];
                __syncthreads();
            }
        }

        // cumprod scan + alloc scatter
        {
            int base = tid*4;
            unsigned long long p0=s_pack[base],p1=s_pack[base+1],p2=s_pack[base+2],p3=s_pack[base+3];
            float x0=__uint_as_float((unsigned)(p0>>32));
            float x1=__uint_as_float((unsigned)(p1>>32));
            float x2=__uint_as_float((unsigned)(p2>>32));
            float x3=__uint_as_float((unsigned)(p3>>32));
            float c0=x0, c1=c0*x1, c2=c1*x2, c3=c2*x3;
            float t3=c3;
            #pragma unroll
            for (int o=1;o<32;o<<=1){ float n=__shfl_up_sync(0xFFFFFFFFu,t3,o); if (lane>=o) t3*=n; }
            float warpExcl = __shfl_up_sync(0xFFFFFFFFu,t3,1); if (lane==0) warpExcl=1.f;
            if (lane==31) s_wsum2[wid]=t3;
            __syncthreads();
            if (tid<32){
                float w = s_wsum2[tid];
                float tw=w;
                #pragma unroll
                for (int o=1;o<32;o<<=1){ float n=__shfl_up_sync(0xFFFFFFFFu,tw,o); if (tid>=o) tw*=n; }
                float excl = __shfl_up_sync(0xFFFFFFFFu,tw,1); if (tid==0) excl=1.f;
                s_wpre[tid]=excl;
            }
            __syncthreads();
            float pre = s_wpre[wid]*warpExcl;
            int i0=(int)(p0&0xFFFFFFFFull), i1=(int)(p1&0xFFFFFFFFull);
            int i2=(int)(p2&0xFFFFFFFFull), i3=(int)(p3&0xFFFFFFFFull);
            s_a[i0]=(1.f-x0)*pre;
            s_a[i1]=(1.f-x1)*pre*c0;
            s_a[i2]=(1.f-x2)*pre*c1;
            s_a[i3]=(1.f-x3)*pre*c2;
            __syncthreads();
        }

        float ag = g_small[4+head], wg = g_small[6+head];
        float wsum = 0.f;
        for (int m=tid;m<MM;m+=T){
            float a = s_a[m];
            float cw = s_cw[m];
            float w = wg*(ag*a + (1.f-ag)*cw);
            g_ww[head*MM+m] = w;
            out_ww[head*MM+m] = w;
            wsum += w;
            float u = s_usage[m];
            s_usage[m] = u + (1.f - u)*(ag*wg)*a;
        }
        wsum = wred(wsum);
        if (lane==0) red[wid]=wsum;
        __syncthreads();
        if (tid==0){ float s=0; for(int k=0;k<32;k++) s+=red[k]; s_bc=s;}
        __syncthreads();
        float oms = 1.f - s_bc;
        for (int m=tid;m<MM;m+=T)
            out_prec[head*MM+m] = oms*prev_prec[head*MM+m] + g_ww[head*MM+m];
        __syncthreads();
    }
    for (int m=tid;m<MM;m+=T) out_usage[m]=s_usage[m];
}

// ------------- kernel 4: new_memory + fused rdot + new norms ---------------
__global__ void __launch_bounds__(1024) k_newmem(const float* __restrict__ memory,
                                                 float* __restrict__ out_nm){
    __shared__ float s_part[32][5*32];
    int tid=threadIdx.x, lane=tid&31, wid=tid>>5;
    const float4* ev4=(const float4*)g_ev;
    const float4* wv4=(const float4*)g_wv;
    const float4* rk4=(const float4*)g_rk;
    float4 e0=__ldg(&ev4[tid]),      e1=__ldg(&ev4[1024+tid]);
    float4 a0=__ldg(&wv4[tid]),      a1=__ldg(&wv4[1024+tid]);
    float4 k0=__ldg(&rk4[tid]),      k1=__ldg(&rk4[1024+tid]);
    float4 k2=__ldg(&rk4[2048+tid]), k3=__ldg(&rk4[3072+tid]);
    int base = blockIdx.x*32;
    float4 v_next = __ldg((const float4*)(memory+(size_t)base*WORDD) + tid);
    #pragma unroll 1
    for (int ii=0; ii<32; ii++){
        int m = base+ii;
        float4 v = v_next;
        if (ii<31) v_next = __ldg((const float4*)(memory+(size_t)(m+1)*WORDD) + tid);
        float w0=__ldg(&g_ww[m]), w1=__ldg(&g_ww[MM+m]);
        float4 o;
        o.x = v.x*((1.f-w0*e0.x)*(1.f-w1*e1.x)) + w0*a0.x + w1*a1.x;
        o.y = v.y*((1.f-w0*e0.y)*(1.f-w1*e1.y)) + w0*a0.y + w1*a1.y;
        o.z = v.z*((1.f-w0*e0.z)*(1.f-w1*e1.z)) + w0*a0.z + w1*a1.z;
        o.w = v.w*((1.f-w0*e0.w)*(1.f-w1*e1.w)) + w0*a0.w + w1*a1.w;
        ((float4*)(out_nm+(size_t)m*WORDD))[tid]=o;
        float r0 = o.x*k0.x+o.y*k0.y+o.z*k0.z+o.w*k0.w;
        float r1 = o.x*k1.x+o.y*k1.y+o.z*k1.z+o.w*k1.w;
        float r2 = o.x*k2.x+o.y*k2.y+o.z*k2.z+o.w*k2.w;
        float r3 = o.x*k3.x+o.y*k3.y+o.z*k3.z+o.w*k3.w;
        float nn = o.x*o.x+o.y*o.y+o.z*o.z+o.w*o.w;
        float rv = gred4(r0,r1,r2,r3,lane);
        float nv = wred(nn);
        if ((lane&7)==0) s_part[ii][(lane>>3)*32+wid] = rv;
        if (lane==0)     s_part[ii][128+wid] = nv;
    }
    __syncthreads();
    if (tid < 160){
        int row=tid/5, q=tid-row*5;
        float s=0.f;
        #pragma unroll
        for (int k=0;k<32;k++) s += s_part[row][q*32+k];
        int m = base + row;
        if (q<4) g_rdot[q*MM+m]=s; else g_newnorm[m]=sqrtf(s);
    }
}

// ------------- kernel 5: link update + fused fwd_w/bwd_w -------------------
__global__ void __launch_bounds__(512) k_link(const float* __restrict__ prev_link,
                       const float* __restrict__ prev_prec,
                       const float* __restrict__ prev_rw,
                       float* __restrict__ out_link){
    __shared__ float s_fred[LCHUNK][4][16];
    int w = blockIdx.y;
    int chunk = blockIdx.x;
    int i0 = chunk*LCHUNK;
    int tid=threadIdx.x, lane=tid&31, wid=tid>>5;
    const float4* ww4 = (const float4*)(g_ww + w*MM);
    const float4* pp4 = (const float4*)(prev_prec + w*MM);
    const float4* pr4 = (const float4*)prev_rw;
    float4 wwa=__ldg(&ww4[tid]),       wwb=__ldg(&ww4[512+tid]);
    float4 ppa=__ldg(&pp4[tid]),       ppb=__ldg(&pp4[512+tid]);
    float4 pa0=__ldg(&pr4[tid]),       pb0=__ldg(&pr4[512+tid]);
    float4 pa1=__ldg(&pr4[1024+tid]),  pb1=__ldg(&pr4[1536+tid]);
    float4 pa2=__ldg(&pr4[2048+tid]),  pb2=__ldg(&pr4[2560+tid]);
    float4 pa3=__ldg(&pr4[3072+tid]),  pb3=__ldg(&pr4[3584+tid]);
    float bw0[8],bw1[8],bw2[8],bw3[8];
    #pragma unroll
    for (int c=0;c<8;c++){ bw0[c]=0.f;bw1[c]=0.f;bw2[c]=0.f;bw3[c]=0.f; }
    int ja = tid*4, jb = (512+tid)*4;
    const float4* plbase = (const float4*)(prev_link + (size_t)w*MM*MM);
    float4 pA_n = __ldcs(plbase + (size_t)i0*1024 + tid);
    float4 pB_n = __ldcs(plbase + (size_t)i0*1024 + 512 + tid);
    #pragma unroll 1
    for (int ii=0; ii<LCHUNK; ii++){
        int i = i0+ii;
        float4 pA = pA_n, pB = pB_n;
        if (ii<LCHUNK-1){
            pA_n = __ldcs(plbase + (size_t)(i+1)*1024 + tid);
            pB_n = __ldcs(plbase + (size_t)(i+1)*1024 + 512 + tid);
        }
        float wwi = __ldg(&g_ww[w*MM+i]);
        float pri0=__ldg(&prev_rw[i]),      pri1=__ldg(&prev_rw[MM+i]);
        float pri2=__ldg(&prev_rw[2*MM+i]), pri3=__ldg(&prev_rw[3*MM+i]);
        float f0=0.f,f1=0.f,f2=0.f,f3=0.f;
        float4 oA, oB;
        {
            float l = (1.f-wwi-wwa.x)*pA.x + wwi*ppa.x; if (ja+0==i) l=0.f; oA.x=l;
            f0+=pa0.x*l; f1+=pa1.x*l; f2+=pa2.x*l; f3+=pa3.x*l;
            bw0[0]+=pri0*l; bw1[0]+=pri1*l; bw2[0]+=pri2*l; bw3[0]+=pri3*l;
        }
        {
            float l = (1.f-wwi-wwa.y)*pA.y + wwi*ppa.y; if (ja+1==i) l=0.f; oA.y=l;
            f0+=pa0.y*l; f1+=pa1.y*l; f2+=pa2.y*l; f3+=pa3.y*l;
            bw0[1]+=pri0*l; bw1[1]+=pri1*l; bw2[1]+=pri2*l; bw3[1]+=pri3*l;
        }
        {
            float l = (1.f-wwi-wwa.z)*pA.z + wwi*ppa.z; if (ja+2==i) l=0.f; oA.z=l;
            f0+=pa0.z*l; f1+=pa1.z*l; f2+=pa2.z*l; f3+=pa3.z*l;
            bw0[2]+=pri0*l; bw1[2]+=pri1*l; bw2[2]+=pri2*l; bw3[2]+=pri3*l;
        }
        {
            float l = (1.f-wwi-wwa.w)*pA.w + wwi*ppa.w; if (ja+3==i) l=0.f; oA.w=l;
            f0+=pa0.w*l; f1+=pa1.w*l; f2+=pa2.w*l; f3+=pa3.w*l;
            bw0[3]+=pri0*l; bw1[3]+=pri1*l; bw2[3]+=pri2*l; bw3[3]+=pri3*l;
        }
        {
            float l = (1.f-wwi-wwb.x)*pB.x + wwi*ppb.x; if (jb+0==i) l=0.f; oB.x=l;
            f0+=pb0.x*l; f1+=pb1.x*l; f2+=pb2.x*l; f3+=pb3.x*l;
            bw0[4]+=pri0*l; bw1[4]+=pri1*l; bw2[4]+=pri2*l; bw3[4]+=pri3*l;
        }
        {
            float l = (1.f-wwi-wwb.y)*pB.y + wwi*ppb.y; if (jb+1==i) l=0.f; oB.y=l;
            f0+=pb0.y*l; f1+=pb1.y*l; f2+=pb2.y*l; f3+=pb3.y*l;
            bw0[5]+=pri0*l; bw1[5]+=pri1*l; bw2[5]+=pri2*l; bw3[5]+=pri3*l;
        }
        {
            float l = (1.f-wwi-wwb.z)*pB.z + wwi*ppb.z; if (jb+2==i) l=0.f; oB.z=l;
            f0+=pb0.z*l; f1+=pb1.z*l; f2+=pb2.z*l; f3+=pb3.z*l;
            bw0[6]+=pri0*l; bw1[6]+=pri1*l; bw2[6]+=pri2*l; bw3[6]+=pri3*l;
        }
        {
            float l = (1.f-wwi-wwb.w)*pB.w + wwi*ppb.w; if (jb+3==i) l=0.f; oB.w=l;
            f0+=pb0.w*l; f1+=pb1.w*l; f2+=pb2.w*l; f3+=pb3.w*l;
            bw0[7]+=pri0*l; bw1[7]+=pri1*l; bw2[7]+=pri2*l; bw3[7]+=pri3*l;
        }
        float4* lo = (float4*)(out_link + ((size_t)w*MM+i)*MM);
        __stcs(lo + tid, oA);
        __stcs(lo + 512 + tid, oB);
        float fv = gred4(f0,f1,f2,f3,lane);
        if ((lane&7)==0) s_fred[ii][lane>>3][wid]=fv;
    }
    __syncthreads();
    if (tid < LCHUNK*4){
        int row = tid>>2, r = tid&3;
        float s=0.f;
        #pragma unroll
        for (int k=0;k<16;k++) s += s_fred[row][r][k];
        g_fwd[(r*NWH + w)*MM + i0 + row] = s;
    }
    size_t pb = (size_t)(w*LNCH + chunk)*4;
    ((float4*)(g_part_bwd + (pb+0)*MM))[tid]     = make_float4(bw0[0],bw0[1],bw0[2],bw0[3]);
    ((float4*)(g_part_bwd + (pb+0)*MM))[512+tid] = make_float4(bw0[4],bw0[5],bw0[6],bw0[7]);
    ((float4*)(g_part_bwd + (pb+1)*MM))[tid]     = make_float4(bw1[0],bw1[1],bw1[2],bw1[3]);
    ((float4*)(g_part_bwd + (pb+1)*MM))[512+tid] = make_float4(bw1[4],bw1[5],bw1[6],bw1[7]);
    ((float4*)(g_part_bwd + (pb+2)*MM))[tid]     = make_float4(bw2[0],bw2[1],bw2[2],bw2[3]);
    ((float4*)(g_part_bwd + (pb+2)*MM))[512+tid] = make_float4(bw2[4],bw2[5],bw2[6],bw2[7]);
    ((float4*)(g_part_bwd + (pb+3)*MM))[tid]     = make_float4(bw3[0],bw3[1],bw3[2],bw3[3]);
    ((float4*)(g_part_bwd + (pb+3)*MM))[512+tid] = make_float4(bw3[4],bw3[5],bw3[6],bw3[7]);
}

// ------------- kernel 6: reduce bwd partials (fixed order, deterministic) --
__global__ void k_bwdreduce(){
    int idx = blockIdx.x*blockDim.x + threadIdx.x; // 32768
    if (idx >= RH*NWH*MM) return;
    int m = idx & (MM-1);
    int w = (idx >> 12) & 1;
    int r = idx >> 13;
    float s=0.f;
    #pragma unroll 8
    for (int t=0;t<LNCH;t++)
        s += g_part_bwd[((size_t)(w*LNCH+t)*4 + r)*MM + m];
    g_bwd[idx]=s;
}

// ------------- kernel 7: read weights — one block per read head -----------
__global__ void k_readw(float* __restrict__ out_rw){
    __shared__ float s_e[MM];
    __shared__ float red[32];
    __shared__ float s_bc;
    const int T = 1024;
    int tid=threadIdx.x, lane=tid&31, wid=tid>>5;
    int r = blockIdx.x;
    float kn=0.f;
    for (int d=tid;d<WORDD;d+=T){ float k=g_rk[r*WORDD+d]; kn+=k*k; }
    kn = wred(kn);
    if (lane==0) red[wid]=kn;
    __syncthreads();
    if (tid==0){ float s=0; for(int k=0;k<32;k++) s+=red[k]; s_bc=sqrtf(s);}
    __syncthreads();
    kn=s_bc;
    float rs = g_small[30+r];
    float mx=-3.4e38f;
    for (int m=tid;m<MM;m+=T){
        float l = g_rdot[r*MM+m]/(kn*g_newnorm[m])*rs;
        mx=fmaxf(mx,l);
    }
    #pragma unroll
    for (int o=16;o;o>>=1) mx=fmaxf(mx,__shfl_xor_sync(0xFFFFFFFFu,mx,o));
    if (lane==0) red[wid]=mx;
    __syncthreads();
    if (tid==0){ float s=-3.4e38f; for(int k=0;k<32;k++) s=fmaxf(s,red[k]); s_bc=s;}
    __syncthreads();
    mx=s_bc;
    float sume=0.f;
    for (int m=tid;m<MM;m+=T){
        float l = g_rdot[r*MM+m]/(kn*g_newnorm[m])*rs;
        float e = expf(l-mx);
        s_e[m]=e; sume+=e;
    }
    sume = wred(sume);
    if (lane==0) red[wid]=sume;
    __syncthreads();
    if (tid==0){ float s=0; for(int k=0;k<32;k++) s+=red[k]; s_bc=s;}
    __syncthreads();
    float inv = 1.f/s_bc;
    float bm0=g_small[8+r*5+0], bm1=g_small[8+r*5+1];
    float fm0=g_small[8+r*5+2], fm1=g_small[8+r*5+3];
    float cm =g_small[8+r*5+4];
    for (int m=tid;m<MM;m+=T){
        float v = bm0*g_bwd[(r*2+0)*MM+m] + bm1*g_bwd[(r*2+1)*MM+m]
                + fm0*g_fwd[(r*2+0)*MM+m] + fm1*g_fwd[(r*2+1)*MM+m]
                + cm*s_e[m]*inv;
        g_rw[r*MM+m]=v; out_rw[r*MM+m]=v;
    }
}

// ------------- kernel 8: read_words partials -------------------------------
__global__ void k_readwords(const float* __restrict__ nm){
    __shared__ float s_rw[4][256];
    int d = blockIdx.x*256 + threadIdx.x;
    int m0 = blockIdx.y*256;
    #pragma unroll
    for (int r=0;r<4;r++) s_rw[r][threadIdx.x] = g_rw[r*MM + m0 + threadIdx.x];
    __syncthreads();
    float a0=0,a1=0,a2=0,a3=0;
    #pragma unroll 4
    for (int mm=0;mm<256;mm++){
        float v = nm[(size_t)(m0+mm)*WORDD + d];
        a0+=s_rw[0][mm]*v; a1+=s_rw[1][mm]*v; a2+=s_rw[2][mm]*v; a3+=s_rw[3][mm]*v;
    }
    g_part_rw[(blockIdx.y*4+0)*WORDD+d]=a0;
    g_part_rw[(blockIdx.y*4+1)*WORDD+d]=a1;
    g_part_rw[(blockIdx.y*4+2)*WORDD+d]=a2;
    g_part_rw[(blockIdx.y*4+3)*WORDD+d]=a3;
}

// ------------- kernel 9: reduce read_words partials ------------------------
__global__ void k_rwreduce(float* __restrict__ out_rwords){
    int idx = blockIdx.x*blockDim.x+threadIdx.x; // 16384
    if (idx >= RH*WORDD) return;
    int r = idx >> 12; int d = idx & (WORDD-1);
    float s=0.f;
    #pragma unroll
    for (int t=0;t<16;t++) s += g_part_rw[(t*4+r)*WORDD+d];
    out_rwords[idx]=s;
}

// ---------------------------------------------------------------------------
extern "C" void kernel_launch(void* const* d_in, const int* in_sizes, int n_in,
                              void* d_out, int out_size) {
    const float* x      = (const float*)d_in[0];
    const float* memory = (const float*)d_in[1];
    const float* prw    = (const float*)d_in[2];
    const float* pww    = (const float*)d_in[3];
    const float* plink  = (const float*)d_in[4];
    const float* pprec  = (const float*)d_in[5];
    const float* pusage = (const float*)d_in[6];

    float* out = (float*)d_out;
    float* o_rwords = out;                            // 4*4096
    float* o_nm     = out + 16384;                    // 4096*4096
    float* o_rw     = out + 16384 + 16777216;         // 4*4096
    float* o_ww     = o_rw + 16384;                   // 2*4096
    float* o_link   = o_ww + 8192;                    // 2*4096*4096
    float* o_prec   = o_link + 33554432;              // 2*4096
    float* o_usage  = o_prec + 8192;                  // 4096

    cudaFuncSetAttribute(k_small, cudaFuncAttributeMaxDynamicSharedMemorySize, 6*MM*4);

    // side stream + events: fork ONLY link ∥ newmem
    cudaStream_t s2;
    cudaStreamCreateWithFlags(&s2, cudaStreamNonBlocking);
    cudaEvent_t eS, eL;
    cudaEventCreateWithFlags(&eS, cudaEventDisableTiming);
    cudaEventCreateWithFlags(&eL, cudaEventDisableTiming);

    // 1. all linears
    {
        int warps = 40994;
        int blocks = (warps*32 + 255)/256;
        k_matvec<<<blocks, 256>>>(x,
            (const float*)d_in[7],  (const float*)d_in[8],
            (const float*)d_in[9],  (const float*)d_in[10],
            (const float*)d_in[11], (const float*)d_in[12],
            (const float*)d_in[13], (const float*)d_in[14],
            (const float*)d_in[15], (const float*)d_in[16],
            (const float*)d_in[17], (const float*)d_in[18],
            (const float*)d_in[19], (const float*)d_in[20],
            (const float*)d_in[21], (const float*)d_in[22],
            (const float*)d_in[23], (const float*)d_in[24],
            (const float*)d_in[25], (const float*)d_in[26]);
    }
    // 2. write-key similarity dot + mem norms
    k_memdot<<<128, 1024>>>(memory);
    // 3. serial core
    k_small<<<1, 1024, 6*MM*4>>>(prw, pww, pprec, pusage, o_ww, o_prec, o_usage);
    cudaEventRecord(eS, 0);
    // 5. link on s2 (needs g_ww)
    cudaStreamWaitEvent(s2, eS, 0);
    k_link<<<dim3(LNCH,2), 512, 0, s2>>>(plink, pprec, prw, o_link);
    cudaEventRecord(eL, s2);
    // 4. newmem on main, concurrent with link
    k_newmem<<<128, 1024>>>(memory, o_nm);
    // join
    cudaStreamWaitEvent(0, eL, 0);
    // 6. bwd partial reduce
    k_bwdreduce<<<128, 256>>>();
    // 7. read weights (4 independent head-blocks)
    k_readw<<<4, 1024>>>(o_rw);
    // 8-9. read words
    k_readwords<<<dim3(16,16), 256>>>(o_nm);
    k_rwreduce<<<64, 256>>>(o_rwords);
}